// round 2
// baseline (speedup 1.0000x reference)
#include <cuda_runtime.h>
#include <math.h>

// Problem constants
constexpr int B_   = 16;
constexpr int C_   = 512;
constexpr int MID_ = 256;
constexpr int N_   = 2048;
constexpr float EPS_ = 1e-5f;

// Tiling
constexpr int BM = 64;
constexpr int BN = 64;
constexpr int BK = 16;
constexpr int WPAD = BM + 4;   // padded row (in floats) for transposed tiles; keeps 16B alignment (68*4=272)

// Scratch (device globals: allocation inside kernel_launch is forbidden)
__device__ float g_q[(size_t)B_ * MID_ * N_];     // 33.5 MB
__device__ float g_k[(size_t)B_ * MID_ * N_];     // 33.5 MB
__device__ float g_v[(size_t)B_ * MID_ * N_];     // 33.5 MB
__device__ float g_s[(size_t)B_ * N_ * N_];       // 268 MB raw scores
__device__ float g_cmax[B_ * N_];
__device__ float g_csum[B_ * N_];
__device__ float g_ctx[(size_t)B_ * MID_ * N_];   // 33.5 MB

// ---------------------------------------------------------------------------
// Kernel 1: fused QKV projection.
//   z = W[mid,C] @ x[b,C,N]  (+bias), then eval BatchNorm + ReLU for q,k.
//   One x tile in smem feeds all three weight sets.
// grid: (N/BN, MID/BM, B), block: 256
// ---------------------------------------------------------------------------
__global__ __launch_bounds__(256) void proj3_kernel(
    const float* __restrict__ x,
    const float* __restrict__ wq, const float* __restrict__ bq,
    const float* __restrict__ gq, const float* __restrict__ betaq,
    const float* __restrict__ mq, const float* __restrict__ vq,
    const float* __restrict__ wk, const float* __restrict__ bk,
    const float* __restrict__ gk, const float* __restrict__ betak,
    const float* __restrict__ mk, const float* __restrict__ vk,
    const float* __restrict__ wv, const float* __restrict__ bv)
{
    __shared__ __align__(16) float Wq[BK * WPAD];
    __shared__ __align__(16) float Wk[BK * WPAD];
    __shared__ __align__(16) float Wv[BK * WPAD];
    __shared__ __align__(16) float Xs[BK * BN];

    const int b  = blockIdx.z;
    const int m0 = blockIdx.y * BM;
    const int n0 = blockIdx.x * BN;
    const int tid = threadIdx.x;
    const int ty = tid >> 4, tx = tid & 15;

    float aq[4][4] = {}, ak[4][4] = {}, av[4][4] = {};
    const float* xb = x + (size_t)b * C_ * N_;

    for (int k0 = 0; k0 < C_; k0 += BK) {
        #pragma unroll
        for (int t = 0; t < 4; t++) {
            int idx = t * 256 + tid;
            int r = idx >> 4, cc = idx & 15;
            size_t off = (size_t)(m0 + r) * C_ + (k0 + cc);
            Wq[cc * WPAD + r] = wq[off];
            Wk[cc * WPAD + r] = wk[off];
            Wv[cc * WPAD + r] = wv[off];
        }
        #pragma unroll
        for (int t = 0; t < 4; t++) {
            int idx = t * 256 + tid;
            int kk = idx >> 6, j = idx & 63;
            Xs[kk * BN + j] = xb[(size_t)(k0 + kk) * N_ + n0 + j];
        }
        __syncthreads();
        #pragma unroll
        for (int kk = 0; kk < BK; kk++) {
            float4 x4 = *reinterpret_cast<const float4*>(&Xs[kk * BN + tx * 4]);
            float4 q4 = *reinterpret_cast<const float4*>(&Wq[kk * WPAD + ty * 4]);
            float4 k4 = *reinterpret_cast<const float4*>(&Wk[kk * WPAD + ty * 4]);
            float4 v4 = *reinterpret_cast<const float4*>(&Wv[kk * WPAD + ty * 4]);
            float xv[4] = {x4.x, x4.y, x4.z, x4.w};
            float qv[4] = {q4.x, q4.y, q4.z, q4.w};
            float kv[4] = {k4.x, k4.y, k4.z, k4.w};
            float vv[4] = {v4.x, v4.y, v4.z, v4.w};
            #pragma unroll
            for (int i = 0; i < 4; i++)
                #pragma unroll
                for (int j = 0; j < 4; j++) {
                    aq[i][j] = fmaf(qv[i], xv[j], aq[i][j]);
                    ak[i][j] = fmaf(kv[i], xv[j], ak[i][j]);
                    av[i][j] = fmaf(vv[i], xv[j], av[i][j]);
                }
        }
        __syncthreads();
    }

    #pragma unroll
    for (int i = 0; i < 4; i++) {
        int m = m0 + ty * 4 + i;
        float invq = gq[m] * rsqrtf(vq[m] + EPS_);
        float cq   = betaq[m] - mq[m] * invq;
        float invk = gk[m] * rsqrtf(vk[m] + EPS_);
        float ck   = betak[m] - mk[m] * invk;
        float bqv = bq[m], bkv = bk[m], bvv = bv[m];
        size_t base = ((size_t)b * MID_ + m) * N_ + n0 + tx * 4;
        #pragma unroll
        for (int j = 0; j < 4; j++) {
            float zq = (aq[i][j] + bqv) * invq + cq;
            float zk = (ak[i][j] + bkv) * invk + ck;
            g_q[base + j] = zq > 0.0f ? zq : 0.0f;
            g_k[base + j] = zk > 0.0f ? zk : 0.0f;
            g_v[base + j] = av[i][j] + bvv;
        }
    }
}

// ---------------------------------------------------------------------------
// Kernel 2: S[b,i,j] = (1/16) * sum_m q[b,m,i] * k[b,m,j]
// grid: (N/BN, N/BM, B), block: 256
// ---------------------------------------------------------------------------
__global__ __launch_bounds__(256) void scores_kernel()
{
    __shared__ __align__(16) float Qs[BK * BN];
    __shared__ __align__(16) float Ks[BK * BN];

    const int b  = blockIdx.z;
    const int i0 = blockIdx.y * BM;
    const int j0 = blockIdx.x * BN;
    const int tid = threadIdx.x;
    const int ty = tid >> 4, tx = tid & 15;

    float acc[4][4] = {};
    const float* qb = g_q + (size_t)b * MID_ * N_;
    const float* kb = g_k + (size_t)b * MID_ * N_;

    for (int k0 = 0; k0 < MID_; k0 += BK) {
        #pragma unroll
        for (int t = 0; t < 4; t++) {
            int idx = t * 256 + tid;
            int kk = idx >> 6, c = idx & 63;
            Qs[kk * BN + c] = qb[(size_t)(k0 + kk) * N_ + i0 + c];
            Ks[kk * BN + c] = kb[(size_t)(k0 + kk) * N_ + j0 + c];
        }
        __syncthreads();
        #pragma unroll
        for (int kk = 0; kk < BK; kk++) {
            float4 q4 = *reinterpret_cast<const float4*>(&Qs[kk * BN + ty * 4]);
            float4 k4 = *reinterpret_cast<const float4*>(&Ks[kk * BN + tx * 4]);
            float qv[4] = {q4.x, q4.y, q4.z, q4.w};
            float kv[4] = {k4.x, k4.y, k4.z, k4.w};
            #pragma unroll
            for (int i = 0; i < 4; i++)
                #pragma unroll
                for (int j = 0; j < 4; j++)
                    acc[i][j] = fmaf(qv[i], kv[j], acc[i][j]);
        }
        __syncthreads();
    }

    float* sb = g_s + (size_t)b * N_ * N_;
    #pragma unroll
    for (int i = 0; i < 4; i++) {
        size_t row = (size_t)(i0 + ty * 4 + i) * N_ + j0 + tx * 4;
        float4 st;
        st.x = acc[i][0] * 0.0625f;
        st.y = acc[i][1] * 0.0625f;
        st.z = acc[i][2] * 0.0625f;
        st.w = acc[i][3] * 0.0625f;
        *reinterpret_cast<float4*>(&sb[row]) = st;
    }
}

// ---------------------------------------------------------------------------
// Kernel 3: per-column (over i) online max + sum-exp for softmax over axis=1.
// grid: (N/32, B), block: (32, 8)
// ---------------------------------------------------------------------------
__global__ __launch_bounds__(256) void colreduce_kernel()
{
    const int b = blockIdx.y;
    const int tx = threadIdx.x;            // j within tile of 32
    const int iy = threadIdx.y;            // i-strided group of 8
    const int j = blockIdx.x * 32 + tx;
    const float* sb = g_s + (size_t)b * N_ * N_;

    float m = -3.0e38f, sum = 0.0f;
    for (int i = iy; i < N_; i += 8) {
        float s = sb[(size_t)i * N_ + j];
        float mn = fmaxf(m, s);
        sum = sum * __expf(m - mn) + __expf(s - mn);
        m = mn;
    }

    __shared__ float sm[8][32], ss[8][32];
    sm[iy][tx] = m;
    ss[iy][tx] = sum;
    __syncthreads();
    if (iy == 0) {
        float M = sm[0][tx], S = ss[0][tx];
        #pragma unroll
        for (int r = 1; r < 8; r++) {
            float m2 = sm[r][tx], s2 = ss[r][tx];
            float mn = fmaxf(M, m2);
            S = S * __expf(M - mn) + s2 * __expf(m2 - mn);
            M = mn;
        }
        g_cmax[b * N_ + j] = M;
        g_csum[b * N_ + j] = S;
    }
}

// ---------------------------------------------------------------------------
// Kernel 4: ctx[b,c,j] = sum_i v[b,c,i] * softmax_i(S)[b,i,j]
//   exp/normalize fused into S-tile load.
// grid: (N/BN, MID/BM, B), block: 256
// ---------------------------------------------------------------------------
__global__ __launch_bounds__(256) void ctx_kernel()
{
    __shared__ __align__(16) float Vt[BK * WPAD];
    __shared__ __align__(16) float Ps[BK * BN];
    __shared__ float cmS[BN], ciS[BN];

    const int b  = blockIdx.z;
    const int c0 = blockIdx.y * BM;
    const int j0 = blockIdx.x * BN;
    const int tid = threadIdx.x;
    const int ty = tid >> 4, tx = tid & 15;

    if (tid < BN) {
        cmS[tid] = g_cmax[b * N_ + j0 + tid];
        ciS[tid] = 1.0f / g_csum[b * N_ + j0 + tid];
    }
    __syncthreads();

    float acc[4][4] = {};
    const float* vb = g_v + (size_t)b * MID_ * N_;
    const float* sb = g_s + (size_t)b * N_ * N_;

    for (int k0 = 0; k0 < N_; k0 += BK) {
        #pragma unroll
        for (int t = 0; t < 4; t++) {
            int idx = t * 256 + tid;
            int r = idx >> 4, cc = idx & 15;
            Vt[cc * WPAD + r] = vb[(size_t)(c0 + r) * N_ + k0 + cc];
        }
        #pragma unroll
        for (int t = 0; t < 4; t++) {
            int idx = t * 256 + tid;
            int kk = idx >> 6, j = idx & 63;
            float s = sb[(size_t)(k0 + kk) * N_ + j0 + j];
            Ps[kk * BN + j] = __expf(s - cmS[j]) * ciS[j];
        }
        __syncthreads();
        #pragma unroll
        for (int kk = 0; kk < BK; kk++) {
            float4 v4 = *reinterpret_cast<const float4*>(&Vt[kk * WPAD + ty * 4]);
            float4 p4 = *reinterpret_cast<const float4*>(&Ps[kk * BN + tx * 4]);
            float vv[4] = {v4.x, v4.y, v4.z, v4.w};
            float pv[4] = {p4.x, p4.y, p4.z, p4.w};
            #pragma unroll
            for (int i = 0; i < 4; i++)
                #pragma unroll
                for (int j = 0; j < 4; j++)
                    acc[i][j] = fmaf(vv[i], pv[j], acc[i][j]);
        }
        __syncthreads();
    }

    #pragma unroll
    for (int i = 0; i < 4; i++) {
        size_t base = ((size_t)b * MID_ + c0 + ty * 4 + i) * N_ + j0 + tx * 4;
        float4 st = {acc[i][0], acc[i][1], acc[i][2], acc[i][3]};
        *reinterpret_cast<float4*>(&g_ctx[base]) = st;
    }
}

// ---------------------------------------------------------------------------
// Kernel 5: out[b,c,n] = x[b,c,n] + sum_m wo[c,m]*ctx[b,m,n] + bo[c]
// grid: (N/BN, C/BM, B), block: 256
// ---------------------------------------------------------------------------
__global__ __launch_bounds__(256) void out_kernel(
    const float* __restrict__ x,
    const float* __restrict__ wo,
    const float* __restrict__ bo,
    float* __restrict__ out)
{
    __shared__ __align__(16) float Wt[BK * WPAD];
    __shared__ __align__(16) float Cs[BK * BN];

    const int b  = blockIdx.z;
    const int c0 = blockIdx.y * BM;
    const int n0 = blockIdx.x * BN;
    const int tid = threadIdx.x;
    const int ty = tid >> 4, tx = tid & 15;

    float acc[4][4] = {};

    for (int k0 = 0; k0 < MID_; k0 += BK) {
        #pragma unroll
        for (int t = 0; t < 4; t++) {
            int idx = t * 256 + tid;
            int r = idx >> 4, cc = idx & 15;
            Wt[cc * WPAD + r] = wo[(size_t)(c0 + r) * MID_ + k0 + cc];
        }
        #pragma unroll
        for (int t = 0; t < 4; t++) {
            int idx = t * 256 + tid;
            int kk = idx >> 6, j = idx & 63;
            Cs[kk * BN + j] = g_ctx[((size_t)b * MID_ + k0 + kk) * N_ + n0 + j];
        }
        __syncthreads();
        #pragma unroll
        for (int kk = 0; kk < BK; kk++) {
            float4 w4 = *reinterpret_cast<const float4*>(&Wt[kk * WPAD + ty * 4]);
            float4 c4 = *reinterpret_cast<const float4*>(&Cs[kk * BN + tx * 4]);
            float wv[4] = {w4.x, w4.y, w4.z, w4.w};
            float cv[4] = {c4.x, c4.y, c4.z, c4.w};
            #pragma unroll
            for (int i = 0; i < 4; i++)
                #pragma unroll
                for (int j = 0; j < 4; j++)
                    acc[i][j] = fmaf(wv[i], cv[j], acc[i][j]);
        }
        __syncthreads();
    }

    #pragma unroll
    for (int i = 0; i < 4; i++) {
        int c = c0 + ty * 4 + i;
        float bov = bo[c];
        size_t base = ((size_t)b * C_ + c) * N_ + n0 + tx * 4;
        float4 xr = *reinterpret_cast<const float4*>(&x[base]);
        float4 st;
        st.x = acc[i][0] + bov + xr.x;
        st.y = acc[i][1] + bov + xr.y;
        st.z = acc[i][2] + bov + xr.z;
        st.w = acc[i][3] + bov + xr.w;
        *reinterpret_cast<float4*>(&out[base]) = st;
    }
}

// ---------------------------------------------------------------------------
extern "C" void kernel_launch(void* const* d_in, const int* in_sizes, int n_in,
                              void* d_out, int out_size)
{
    (void)in_sizes; (void)n_in; (void)out_size;
    const float* x     = (const float*)d_in[0];
    const float* wq    = (const float*)d_in[1];
    const float* bq    = (const float*)d_in[2];
    const float* gq    = (const float*)d_in[3];
    const float* betaq = (const float*)d_in[4];
    const float* wk    = (const float*)d_in[5];
    const float* bk    = (const float*)d_in[6];
    const float* gk    = (const float*)d_in[7];
    const float* betak = (const float*)d_in[8];
    const float* wv    = (const float*)d_in[9];
    const float* bv    = (const float*)d_in[10];
    const float* wo    = (const float*)d_in[11];
    const float* bo    = (const float*)d_in[12];
    const float* mq    = (const float*)d_in[13];
    const float* vq    = (const float*)d_in[14];
    const float* mk    = (const float*)d_in[15];
    const float* vk    = (const float*)d_in[16];
    float* out = (float*)d_out;

    dim3 blk(256);
    proj3_kernel<<<dim3(N_/BN, MID_/BM, B_), blk>>>(
        x, wq, bq, gq, betaq, mq, vq, wk, bk, gk, betak, mk, vk, wv, bv);
    scores_kernel<<<dim3(N_/BN, N_/BM, B_), blk>>>();
    colreduce_kernel<<<dim3(N_/32, B_), dim3(32, 8)>>>();
    ctx_kernel<<<dim3(N_/BN, MID_/BM, B_), blk>>>();
    out_kernel<<<dim3(N_/BN, C_/BM, B_), blk>>>(x, wo, bo, out);
}

// round 3
// speedup vs baseline: 1.8628x; 1.8628x over previous
#include <cuda_runtime.h>
#include <math.h>

// Problem constants
constexpr int B_   = 16;
constexpr int C_   = 512;
constexpr int MID_ = 256;
constexpr int N_   = 2048;
constexpr float EPS_ = 1e-5f;

// SIMT tiling (proj3 / out kernels)
constexpr int BM = 64;
constexpr int BN = 64;
constexpr int BK = 16;
constexpr int WPAD = BM + 4;

// MMA tiling (scores / ctx kernels)
constexpr int TBM = 128;
constexpr int TBN = 128;
constexpr int TBK = 16;
constexpr int SSTRIDE = TBM + 8;   // 136 floats: 16B-aligned rows, stride%32==8 -> conflict-free frags

// Scratch (device globals: allocation inside kernel_launch is forbidden)
__device__ float g_q[(size_t)B_ * MID_ * N_];
__device__ float g_k[(size_t)B_ * MID_ * N_];
__device__ float g_v[(size_t)B_ * MID_ * N_];
__device__ float g_s[(size_t)B_ * N_ * N_];
__device__ float g_cmax[B_ * N_];
__device__ float g_csum[B_ * N_];
__device__ float g_ctx[(size_t)B_ * MID_ * N_];

// ---------------------------------------------------------------------------
// tf32 warp MMA: D(16x8) += A(16x8,row) * B(8x8,col)
// ---------------------------------------------------------------------------
__device__ __forceinline__ void mma_tf32(float c[4], const float a[4], const float b[2])
{
    asm volatile(
        "mma.sync.aligned.m16n8k8.row.col.f32.tf32.tf32.f32 "
        "{%0,%1,%2,%3}, {%4,%5,%6,%7}, {%8,%9}, {%0,%1,%2,%3};\n"
        : "+f"(c[0]), "+f"(c[1]), "+f"(c[2]), "+f"(c[3])
        : "r"(__float_as_uint(a[0])), "r"(__float_as_uint(a[1])),
          "r"(__float_as_uint(a[2])), "r"(__float_as_uint(a[3])),
          "r"(__float_as_uint(b[0])), "r"(__float_as_uint(b[1])));
}

// ---------------------------------------------------------------------------
// Kernel 1: fused QKV projection (SIMT). grid (N/BN, MID/BM, B), 256 thr.
// ---------------------------------------------------------------------------
__global__ __launch_bounds__(256) void proj3_kernel(
    const float* __restrict__ x,
    const float* __restrict__ wq, const float* __restrict__ bq,
    const float* __restrict__ gq, const float* __restrict__ betaq,
    const float* __restrict__ mq, const float* __restrict__ vq,
    const float* __restrict__ wk, const float* __restrict__ bk,
    const float* __restrict__ gk, const float* __restrict__ betak,
    const float* __restrict__ mk, const float* __restrict__ vk,
    const float* __restrict__ wv, const float* __restrict__ bv)
{
    __shared__ __align__(16) float Wq[BK * WPAD];
    __shared__ __align__(16) float Wk[BK * WPAD];
    __shared__ __align__(16) float Wv[BK * WPAD];
    __shared__ __align__(16) float Xs[BK * BN];

    const int b  = blockIdx.z;
    const int m0 = blockIdx.y * BM;
    const int n0 = blockIdx.x * BN;
    const int tid = threadIdx.x;
    const int ty = tid >> 4, tx = tid & 15;

    float aq[4][4] = {}, ak[4][4] = {}, av[4][4] = {};
    const float* xb = x + (size_t)b * C_ * N_;

    for (int k0 = 0; k0 < C_; k0 += BK) {
        #pragma unroll
        for (int t = 0; t < 4; t++) {
            int idx = t * 256 + tid;
            int r = idx >> 4, cc = idx & 15;
            size_t off = (size_t)(m0 + r) * C_ + (k0 + cc);
            Wq[cc * WPAD + r] = wq[off];
            Wk[cc * WPAD + r] = wk[off];
            Wv[cc * WPAD + r] = wv[off];
        }
        #pragma unroll
        for (int t = 0; t < 4; t++) {
            int idx = t * 256 + tid;
            int kk = idx >> 6, j = idx & 63;
            Xs[kk * BN + j] = xb[(size_t)(k0 + kk) * N_ + n0 + j];
        }
        __syncthreads();
        #pragma unroll
        for (int kk = 0; kk < BK; kk++) {
            float4 x4 = *reinterpret_cast<const float4*>(&Xs[kk * BN + tx * 4]);
            float4 q4 = *reinterpret_cast<const float4*>(&Wq[kk * WPAD + ty * 4]);
            float4 k4 = *reinterpret_cast<const float4*>(&Wk[kk * WPAD + ty * 4]);
            float4 v4 = *reinterpret_cast<const float4*>(&Wv[kk * WPAD + ty * 4]);
            float xv[4] = {x4.x, x4.y, x4.z, x4.w};
            float qv[4] = {q4.x, q4.y, q4.z, q4.w};
            float kv[4] = {k4.x, k4.y, k4.z, k4.w};
            float vv[4] = {v4.x, v4.y, v4.z, v4.w};
            #pragma unroll
            for (int i = 0; i < 4; i++)
                #pragma unroll
                for (int j = 0; j < 4; j++) {
                    aq[i][j] = fmaf(qv[i], xv[j], aq[i][j]);
                    ak[i][j] = fmaf(kv[i], xv[j], ak[i][j]);
                    av[i][j] = fmaf(vv[i], xv[j], av[i][j]);
                }
        }
        __syncthreads();
    }

    #pragma unroll
    for (int i = 0; i < 4; i++) {
        int m = m0 + ty * 4 + i;
        float invq = gq[m] * rsqrtf(vq[m] + EPS_);
        float cq   = betaq[m] - mq[m] * invq;
        float invk = gk[m] * rsqrtf(vk[m] + EPS_);
        float ck   = betak[m] - mk[m] * invk;
        float bqv = bq[m], bkv = bk[m], bvv = bv[m];
        size_t base = ((size_t)b * MID_ + m) * N_ + n0 + tx * 4;
        #pragma unroll
        for (int j = 0; j < 4; j++) {
            float zq = (aq[i][j] + bqv) * invq + cq;
            float zk = (ak[i][j] + bkv) * invk + ck;
            g_q[base + j] = zq > 0.0f ? zq : 0.0f;
            g_k[base + j] = zk > 0.0f ? zk : 0.0f;
            g_v[base + j] = av[i][j] + bvv;
        }
    }
}

// ---------------------------------------------------------------------------
// Kernel 2 (tf32 MMA): S[b,i,j] = (1/16) sum_m q[b,m,i] k[b,m,j]
// grid (N/128, N/128, B), 256 thr (8 warps in 2x4), 4x4 m16n8k8 per warp.
// ---------------------------------------------------------------------------
__global__ __launch_bounds__(256, 2) void scores_mma()
{
    __shared__ __align__(16) float As[2][TBK][SSTRIDE];
    __shared__ __align__(16) float Bs[2][TBK][SSTRIDE];

    const int b  = blockIdx.z;
    const int i0 = blockIdx.y * TBM;
    const int j0 = blockIdx.x * TBN;
    const int tid  = threadIdx.x;
    const int lane = tid & 31, wid = tid >> 5;
    const int wm = wid & 1, wn = wid >> 1;      // warp tile: rows wm*64, cols wn*32
    const int g = lane >> 2, tg = lane & 3;

    const float* qb = g_q + (size_t)b * MID_ * N_;
    const float* kb = g_k + (size_t)b * MID_ * N_;

    float acc[4][4][4] = {};

    // stage tile k0 into buffer buf
    auto load_tile = [&](int buf, int k0) {
        #pragma unroll
        for (int r = 0; r < 2; r++) {
            int f  = tid + r * 256;          // 0..511 float4 slots
            int kk = f >> 5, c4 = (f & 31) << 2;
            float4 qv = *reinterpret_cast<const float4*>(&qb[(size_t)(k0 + kk) * N_ + i0 + c4]);
            float4 kv = *reinterpret_cast<const float4*>(&kb[(size_t)(k0 + kk) * N_ + j0 + c4]);
            *reinterpret_cast<float4*>(&As[buf][kk][c4]) = qv;
            *reinterpret_cast<float4*>(&Bs[buf][kk][c4]) = kv;
        }
    };

    load_tile(0, 0);
    __syncthreads();

    for (int k0 = 0; k0 < MID_; k0 += TBK) {
        const int buf = (k0 / TBK) & 1;
        if (k0 + TBK < MID_) load_tile(buf ^ 1, k0 + TBK);

        #pragma unroll
        for (int ks = 0; ks < TBK / 8; ks++) {
            const int kb8 = ks * 8;
            float af[4][4], bf[4][2];
            #pragma unroll
            for (int mt = 0; mt < 4; mt++) {
                int row = wm * 64 + mt * 16 + g;
                af[mt][0] = As[buf][kb8 + tg][row];
                af[mt][1] = As[buf][kb8 + tg][row + 8];
                af[mt][2] = As[buf][kb8 + tg + 4][row];
                af[mt][3] = As[buf][kb8 + tg + 4][row + 8];
            }
            #pragma unroll
            for (int nt = 0; nt < 4; nt++) {
                int col = wn * 32 + nt * 8 + g;
                bf[nt][0] = Bs[buf][kb8 + tg][col];
                bf[nt][1] = Bs[buf][kb8 + tg + 4][col];
            }
            #pragma unroll
            for (int mt = 0; mt < 4; mt++)
                #pragma unroll
                for (int nt = 0; nt < 4; nt++)
                    mma_tf32(acc[mt][nt], af[mt], bf[nt]);
        }
        __syncthreads();
    }

    float* sb = g_s + (size_t)b * N_ * N_;
    #pragma unroll
    for (int mt = 0; mt < 4; mt++) {
        #pragma unroll
        for (int nt = 0; nt < 4; nt++) {
            int row = i0 + wm * 64 + mt * 16 + g;
            int col = j0 + wn * 32 + nt * 8 + tg * 2;
            float2 v0 = {acc[mt][nt][0] * 0.0625f, acc[mt][nt][1] * 0.0625f};
            float2 v1 = {acc[mt][nt][2] * 0.0625f, acc[mt][nt][3] * 0.0625f};
            *reinterpret_cast<float2*>(&sb[(size_t)row * N_ + col]) = v0;
            *reinterpret_cast<float2*>(&sb[(size_t)(row + 8) * N_ + col]) = v1;
        }
    }
}

// ---------------------------------------------------------------------------
// Kernel 3: per-column (over i) online max + sum-exp (softmax over axis=1).
// ---------------------------------------------------------------------------
__global__ __launch_bounds__(256) void colreduce_kernel()
{
    const int b = blockIdx.y;
    const int tx = threadIdx.x;
    const int iy = threadIdx.y;
    const int j = blockIdx.x * 32 + tx;
    const float* sb = g_s + (size_t)b * N_ * N_;

    float m = -3.0e38f, sum = 0.0f;
    for (int i = iy; i < N_; i += 8) {
        float s = sb[(size_t)i * N_ + j];
        float mn = fmaxf(m, s);
        sum = sum * __expf(m - mn) + __expf(s - mn);
        m = mn;
    }

    __shared__ float sm[8][32], ss[8][32];
    sm[iy][tx] = m;
    ss[iy][tx] = sum;
    __syncthreads();
    if (iy == 0) {
        float M = sm[0][tx], S = ss[0][tx];
        #pragma unroll
        for (int r = 1; r < 8; r++) {
            float m2 = sm[r][tx], s2 = ss[r][tx];
            float mn = fmaxf(M, m2);
            S = S * __expf(M - mn) + s2 * __expf(m2 - mn);
            M = mn;
        }
        g_cmax[b * N_ + j] = M;
        g_csum[b * N_ + j] = S;
    }
}

// ---------------------------------------------------------------------------
// Kernel 4 (tf32 MMA): ctx[b,c,j] = sum_i v[b,c,i] * P[b,i,j],
//   P = exp(S - colmax)/colsum fused into B-tile staging.
// grid (N/128, MID/128, B), 256 thr.
// ---------------------------------------------------------------------------
__global__ __launch_bounds__(256, 2) void ctx_mma()
{
    __shared__ __align__(16) float As[2][TBK][SSTRIDE];   // V^T tile: [i][c]
    __shared__ __align__(16) float Bs[2][TBK][SSTRIDE];   // P tile:  [i][j]
    __shared__ float cmS[TBN], ciS[TBN];

    const int b  = blockIdx.z;
    const int c0 = blockIdx.y * TBM;
    const int j0 = blockIdx.x * TBN;
    const int tid  = threadIdx.x;
    const int lane = tid & 31, wid = tid >> 5;
    const int wm = wid & 1, wn = wid >> 1;
    const int g = lane >> 2, tg = lane & 3;

    const float* vb = g_v + (size_t)b * MID_ * N_;
    const float* sb = g_s + (size_t)b * N_ * N_;

    if (tid < TBN) {
        cmS[tid] = g_cmax[b * N_ + j0 + tid];
        ciS[tid] = 1.0f / g_csum[b * N_ + j0 + tid];
    }
    __syncthreads();

    float acc[4][4][4] = {};

    auto load_tile = [&](int buf, int k0) {
        // V: load rows of v (contiguous in i), transpose into As[i][c]
        #pragma unroll
        for (int r = 0; r < 2; r++) {
            int f = tid + r * 256;             // 0..511
            int c = f >> 2, q4 = (f & 3) << 2; // c row, i offset
            float4 vv = *reinterpret_cast<const float4*>(&vb[(size_t)(c0 + c) * N_ + k0 + q4]);
            As[buf][q4 + 0][c] = vv.x;
            As[buf][q4 + 1][c] = vv.y;
            As[buf][q4 + 2][c] = vv.z;
            As[buf][q4 + 3][c] = vv.w;
        }
        // P: rows of S (contiguous in j), exp+normalize on the fly
        #pragma unroll
        for (int r = 0; r < 2; r++) {
            int f  = tid + r * 256;
            int kk = f >> 5, j4 = (f & 31) << 2;
            float4 s4 = *reinterpret_cast<const float4*>(&sb[(size_t)(k0 + kk) * N_ + j0 + j4]);
            float4 p4;
            p4.x = __expf(s4.x - cmS[j4 + 0]) * ciS[j4 + 0];
            p4.y = __expf(s4.y - cmS[j4 + 1]) * ciS[j4 + 1];
            p4.z = __expf(s4.z - cmS[j4 + 2]) * ciS[j4 + 2];
            p4.w = __expf(s4.w - cmS[j4 + 3]) * ciS[j4 + 3];
            *reinterpret_cast<float4*>(&Bs[buf][kk][j4]) = p4;
        }
    };

    load_tile(0, 0);
    __syncthreads();

    for (int k0 = 0; k0 < N_; k0 += TBK) {
        const int buf = (k0 / TBK) & 1;
        if (k0 + TBK < N_) load_tile(buf ^ 1, k0 + TBK);

        #pragma unroll
        for (int ks = 0; ks < TBK / 8; ks++) {
            const int kb8 = ks * 8;
            float af[4][4], bf[4][2];
            #pragma unroll
            for (int mt = 0; mt < 4; mt++) {
                int row = wm * 64 + mt * 16 + g;
                af[mt][0] = As[buf][kb8 + tg][row];
                af[mt][1] = As[buf][kb8 + tg][row + 8];
                af[mt][2] = As[buf][kb8 + tg + 4][row];
                af[mt][3] = As[buf][kb8 + tg + 4][row + 8];
            }
            #pragma unroll
            for (int nt = 0; nt < 4; nt++) {
                int col = wn * 32 + nt * 8 + g;
                bf[nt][0] = Bs[buf][kb8 + tg][col];
                bf[nt][1] = Bs[buf][kb8 + tg + 4][col];
            }
            #pragma unroll
            for (int mt = 0; mt < 4; mt++)
                #pragma unroll
                for (int nt = 0; nt < 4; nt++)
                    mma_tf32(acc[mt][nt], af[mt], bf[nt]);
        }
        __syncthreads();
    }

    #pragma unroll
    for (int mt = 0; mt < 4; mt++) {
        #pragma unroll
        for (int nt = 0; nt < 4; nt++) {
            int row = c0 + wm * 64 + mt * 16 + g;
            int col = j0 + wn * 32 + nt * 8 + tg * 2;
            float2 v0 = {acc[mt][nt][0], acc[mt][nt][1]};
            float2 v1 = {acc[mt][nt][2], acc[mt][nt][3]};
            *reinterpret_cast<float2*>(&g_ctx[((size_t)b * MID_ + row) * N_ + col]) = v0;
            *reinterpret_cast<float2*>(&g_ctx[((size_t)b * MID_ + row + 8) * N_ + col]) = v1;
        }
    }
}

// ---------------------------------------------------------------------------
// Kernel 5: out = x + wo @ ctx + bo (SIMT). grid (N/BN, C/BM, B), 256 thr.
// ---------------------------------------------------------------------------
__global__ __launch_bounds__(256) void out_kernel(
    const float* __restrict__ x,
    const float* __restrict__ wo,
    const float* __restrict__ bo,
    float* __restrict__ out)
{
    __shared__ __align__(16) float Wt[BK * WPAD];
    __shared__ __align__(16) float Cs[BK * BN];

    const int b  = blockIdx.z;
    const int c0 = blockIdx.y * BM;
    const int n0 = blockIdx.x * BN;
    const int tid = threadIdx.x;
    const int ty = tid >> 4, tx = tid & 15;

    float acc[4][4] = {};

    for (int k0 = 0; k0 < MID_; k0 += BK) {
        #pragma unroll
        for (int t = 0; t < 4; t++) {
            int idx = t * 256 + tid;
            int r = idx >> 4, cc = idx & 15;
            Wt[cc * WPAD + r] = wo[(size_t)(c0 + r) * MID_ + k0 + cc];
        }
        #pragma unroll
        for (int t = 0; t < 4; t++) {
            int idx = t * 256 + tid;
            int kk = idx >> 6, j = idx & 63;
            Cs[kk * BN + j] = g_ctx[((size_t)b * MID_ + k0 + kk) * N_ + n0 + j];
        }
        __syncthreads();
        #pragma unroll
        for (int kk = 0; kk < BK; kk++) {
            float4 w4 = *reinterpret_cast<const float4*>(&Wt[kk * WPAD + ty * 4]);
            float4 c4 = *reinterpret_cast<const float4*>(&Cs[kk * BN + tx * 4]);
            float wv[4] = {w4.x, w4.y, w4.z, w4.w};
            float cv[4] = {c4.x, c4.y, c4.z, c4.w};
            #pragma unroll
            for (int i = 0; i < 4; i++)
                #pragma unroll
                for (int j = 0; j < 4; j++)
                    acc[i][j] = fmaf(wv[i], cv[j], acc[i][j]);
        }
        __syncthreads();
    }

    #pragma unroll
    for (int i = 0; i < 4; i++) {
        int c = c0 + ty * 4 + i;
        float bov = bo[c];
        size_t base = ((size_t)b * C_ + c) * N_ + n0 + tx * 4;
        float4 xr = *reinterpret_cast<const float4*>(&x[base]);
        float4 st;
        st.x = acc[i][0] + bov + xr.x;
        st.y = acc[i][1] + bov + xr.y;
        st.z = acc[i][2] + bov + xr.z;
        st.w = acc[i][3] + bov + xr.w;
        *reinterpret_cast<float4*>(&out[base]) = st;
    }
}

// ---------------------------------------------------------------------------
extern "C" void kernel_launch(void* const* d_in, const int* in_sizes, int n_in,
                              void* d_out, int out_size)
{
    (void)in_sizes; (void)n_in; (void)out_size;
    const float* x     = (const float*)d_in[0];
    const float* wq    = (const float*)d_in[1];
    const float* bq    = (const float*)d_in[2];
    const float* gq    = (const float*)d_in[3];
    const float* betaq = (const float*)d_in[4];
    const float* wk    = (const float*)d_in[5];
    const float* bk    = (const float*)d_in[6];
    const float* gk    = (const float*)d_in[7];
    const float* betak = (const float*)d_in[8];
    const float* wv    = (const float*)d_in[9];
    const float* bv    = (const float*)d_in[10];
    const float* wo    = (const float*)d_in[11];
    const float* bo    = (const float*)d_in[12];
    const float* mq    = (const float*)d_in[13];
    const float* vq    = (const float*)d_in[14];
    const float* mk    = (const float*)d_in[15];
    const float* vk    = (const float*)d_in[16];
    float* out = (float*)d_out;

    dim3 blk(256);
    proj3_kernel<<<dim3(N_/BN, MID_/BM, B_), blk>>>(
        x, wq, bq, gq, betaq, mq, vq, wk, bk, gk, betak, mk, vk, wv, bv);
    scores_mma<<<dim3(N_/TBN, N_/TBM, B_), blk>>>();
    colreduce_kernel<<<dim3(N_/32, B_), dim3(32, 8)>>>();
    ctx_mma<<<dim3(N_/TBN, MID_/TBM, B_), blk>>>();
    out_kernel<<<dim3(N_/BN, C_/BM, B_), blk>>>(x, wo, bo, out);
}

// round 4
// speedup vs baseline: 2.7232x; 1.4619x over previous
#include <cuda_runtime.h>
#include <math.h>

// Problem constants
constexpr int B_   = 16;
constexpr int C_   = 512;
constexpr int MID_ = 256;
constexpr int N_   = 2048;
constexpr float EPS_ = 1e-5f;

// MMA tiling (all GEMM kernels)
constexpr int TBM = 128;
constexpr int TBN = 128;
constexpr int TBK = 16;
constexpr int SSTRIDE = TBM + 8;   // 136: 16B-aligned rows, stride%32==8 -> conflict-free frags

// Scratch
__device__ float g_q[(size_t)B_ * MID_ * N_];
__device__ float g_k[(size_t)B_ * MID_ * N_];
__device__ float g_v[(size_t)B_ * MID_ * N_];
__device__ float g_s[(size_t)B_ * N_ * N_];
__device__ float g_pmax[B_ * 8 * N_];
__device__ float g_psum[B_ * 8 * N_];
__device__ float g_cmax[B_ * N_];
__device__ float g_csum[B_ * N_];
__device__ float g_ctx[(size_t)B_ * MID_ * N_];

// ---------------------------------------------------------------------------
// tf32 warp MMA: D(16x8) += A(16x8,row) * B(8x8,col)
// ---------------------------------------------------------------------------
__device__ __forceinline__ void mma_tf32(float c[4], const float a[4], const float b[2])
{
    asm volatile(
        "mma.sync.aligned.m16n8k8.row.col.f32.tf32.tf32.f32 "
        "{%0,%1,%2,%3}, {%4,%5,%6,%7}, {%8,%9}, {%0,%1,%2,%3};\n"
        : "+f"(c[0]), "+f"(c[1]), "+f"(c[2]), "+f"(c[3])
        : "r"(__float_as_uint(a[0])), "r"(__float_as_uint(a[1])),
          "r"(__float_as_uint(a[2])), "r"(__float_as_uint(a[3])),
          "r"(__float_as_uint(b[0])), "r"(__float_as_uint(b[1])));
}

// ---------------------------------------------------------------------------
// Kernel 1 (tf32 MMA): fused QKV projection.
//   z[m,n] = sum_c W[m,c] x[b,c,n]; epilogue does bias+BN+ReLU (q,k) / bias (v).
//   blockIdx.z = mat*B + b, mat in {0:q, 1:k, 2:v}.
// grid (N/128, MID/128, 3B), 256 thr.
// ---------------------------------------------------------------------------
__global__ __launch_bounds__(256, 2) void proj_mma(
    const float* __restrict__ x,
    const float* __restrict__ wq, const float* __restrict__ bq,
    const float* __restrict__ gq, const float* __restrict__ betaq,
    const float* __restrict__ mq, const float* __restrict__ vq,
    const float* __restrict__ wk, const float* __restrict__ bk,
    const float* __restrict__ gk, const float* __restrict__ betak,
    const float* __restrict__ mk, const float* __restrict__ vk,
    const float* __restrict__ wv, const float* __restrict__ bv)
{
    __shared__ __align__(16) float As[2][TBK][SSTRIDE];   // W^T tile [k][m]
    __shared__ __align__(16) float Bs[2][TBK][SSTRIDE];   // x tile  [k][n]

    const int mat = blockIdx.z / B_;
    const int b   = blockIdx.z % B_;
    const int m0  = blockIdx.y * TBM;
    const int n0  = blockIdx.x * TBN;
    const int tid  = threadIdx.x;
    const int lane = tid & 31, wid = tid >> 5;
    const int wm = wid & 1, wn = wid >> 1;
    const int g = lane >> 2, tg = lane & 3;

    const float* w  = (mat == 0) ? wq : (mat == 1) ? wk : wv;
    const float* xb = x + (size_t)b * C_ * N_;

    float acc[4][4][4] = {};

    auto load_tile = [&](int buf, int k0) {
        #pragma unroll
        for (int r = 0; r < 2; r++) {
            int f = tid + r * 256;
            int m = f >> 2, kq = (f & 3) << 2;
            float4 w4 = *reinterpret_cast<const float4*>(&w[(size_t)(m0 + m) * C_ + k0 + kq]);
            As[buf][kq + 0][m] = w4.x;
            As[buf][kq + 1][m] = w4.y;
            As[buf][kq + 2][m] = w4.z;
            As[buf][kq + 3][m] = w4.w;
        }
        #pragma unroll
        for (int r = 0; r < 2; r++) {
            int f  = tid + r * 256;
            int kk = f >> 5, n4 = (f & 31) << 2;
            *reinterpret_cast<float4*>(&Bs[buf][kk][n4]) =
                *reinterpret_cast<const float4*>(&xb[(size_t)(k0 + kk) * N_ + n0 + n4]);
        }
    };

    load_tile(0, 0);
    __syncthreads();

    for (int k0 = 0; k0 < C_; k0 += TBK) {
        const int buf = (k0 / TBK) & 1;
        if (k0 + TBK < C_) load_tile(buf ^ 1, k0 + TBK);

        #pragma unroll
        for (int ks = 0; ks < TBK / 8; ks++) {
            const int kb8 = ks * 8;
            float af[4][4], bf[4][2];
            #pragma unroll
            for (int mt = 0; mt < 4; mt++) {
                int row = wm * 64 + mt * 16 + g;
                af[mt][0] = As[buf][kb8 + tg][row];
                af[mt][1] = As[buf][kb8 + tg][row + 8];
                af[mt][2] = As[buf][kb8 + tg + 4][row];
                af[mt][3] = As[buf][kb8 + tg + 4][row + 8];
            }
            #pragma unroll
            for (int nt = 0; nt < 4; nt++) {
                int col = wn * 32 + nt * 8 + g;
                bf[nt][0] = Bs[buf][kb8 + tg][col];
                bf[nt][1] = Bs[buf][kb8 + tg + 4][col];
            }
            #pragma unroll
            for (int mt = 0; mt < 4; mt++)
                #pragma unroll
                for (int nt = 0; nt < 4; nt++)
                    mma_tf32(acc[mt][nt], af[mt], bf[nt]);
        }
        __syncthreads();
    }

    float* dst = (mat == 0) ? g_q : (mat == 1) ? g_k : g_v;

    #pragma unroll
    for (int mt = 0; mt < 4; mt++) {
        int r0 = m0 + wm * 64 + mt * 16 + g;
        int r1 = r0 + 8;
        // per-row affine: val = acc*scale + off, then optional ReLU
        float sc0, of0, sc1, of1;
        bool relu = (mat != 2);
        if (mat == 0) {
            float i0 = gq[r0] * rsqrtf(vq[r0] + EPS_);
            float i1 = gq[r1] * rsqrtf(vq[r1] + EPS_);
            sc0 = i0; of0 = (bq[r0] - mq[r0]) * i0 + betaq[r0];
            sc1 = i1; of1 = (bq[r1] - mq[r1]) * i1 + betaq[r1];
        } else if (mat == 1) {
            float i0 = gk[r0] * rsqrtf(vk[r0] + EPS_);
            float i1 = gk[r1] * rsqrtf(vk[r1] + EPS_);
            sc0 = i0; of0 = (bk[r0] - mk[r0]) * i0 + betak[r0];
            sc1 = i1; of1 = (bk[r1] - mk[r1]) * i1 + betak[r1];
        } else {
            sc0 = 1.0f; of0 = bv[r0];
            sc1 = 1.0f; of1 = bv[r1];
        }
        #pragma unroll
        for (int nt = 0; nt < 4; nt++) {
            int col = n0 + wn * 32 + nt * 8 + tg * 2;
            float v00 = acc[mt][nt][0] * sc0 + of0;
            float v01 = acc[mt][nt][1] * sc0 + of0;
            float v10 = acc[mt][nt][2] * sc1 + of1;
            float v11 = acc[mt][nt][3] * sc1 + of1;
            if (relu) {
                v00 = fmaxf(v00, 0.0f); v01 = fmaxf(v01, 0.0f);
                v10 = fmaxf(v10, 0.0f); v11 = fmaxf(v11, 0.0f);
            }
            float2 p0 = {v00, v01}, p1 = {v10, v11};
            *reinterpret_cast<float2*>(&dst[((size_t)b * MID_ + r0) * N_ + col]) = p0;
            *reinterpret_cast<float2*>(&dst[((size_t)b * MID_ + r1) * N_ + col]) = p1;
        }
    }
}

// ---------------------------------------------------------------------------
// Kernel 2 (tf32 MMA): S[b,i,j] = (1/16) sum_m q[b,m,i] k[b,m,j]
// ---------------------------------------------------------------------------
__global__ __launch_bounds__(256, 2) void scores_mma()
{
    __shared__ __align__(16) float As[2][TBK][SSTRIDE];
    __shared__ __align__(16) float Bs[2][TBK][SSTRIDE];

    const int b  = blockIdx.z;
    const int i0 = blockIdx.y * TBM;
    const int j0 = blockIdx.x * TBN;
    const int tid  = threadIdx.x;
    const int lane = tid & 31, wid = tid >> 5;
    const int wm = wid & 1, wn = wid >> 1;
    const int g = lane >> 2, tg = lane & 3;

    const float* qb = g_q + (size_t)b * MID_ * N_;
    const float* kb = g_k + (size_t)b * MID_ * N_;

    float acc[4][4][4] = {};

    auto load_tile = [&](int buf, int k0) {
        #pragma unroll
        for (int r = 0; r < 2; r++) {
            int f  = tid + r * 256;
            int kk = f >> 5, c4 = (f & 31) << 2;
            float4 qv = *reinterpret_cast<const float4*>(&qb[(size_t)(k0 + kk) * N_ + i0 + c4]);
            float4 kv = *reinterpret_cast<const float4*>(&kb[(size_t)(k0 + kk) * N_ + j0 + c4]);
            *reinterpret_cast<float4*>(&As[buf][kk][c4]) = qv;
            *reinterpret_cast<float4*>(&Bs[buf][kk][c4]) = kv;
        }
    };

    load_tile(0, 0);
    __syncthreads();

    for (int k0 = 0; k0 < MID_; k0 += TBK) {
        const int buf = (k0 / TBK) & 1;
        if (k0 + TBK < MID_) load_tile(buf ^ 1, k0 + TBK);

        #pragma unroll
        for (int ks = 0; ks < TBK / 8; ks++) {
            const int kb8 = ks * 8;
            float af[4][4], bf[4][2];
            #pragma unroll
            for (int mt = 0; mt < 4; mt++) {
                int row = wm * 64 + mt * 16 + g;
                af[mt][0] = As[buf][kb8 + tg][row];
                af[mt][1] = As[buf][kb8 + tg][row + 8];
                af[mt][2] = As[buf][kb8 + tg + 4][row];
                af[mt][3] = As[buf][kb8 + tg + 4][row + 8];
            }
            #pragma unroll
            for (int nt = 0; nt < 4; nt++) {
                int col = wn * 32 + nt * 8 + g;
                bf[nt][0] = Bs[buf][kb8 + tg][col];
                bf[nt][1] = Bs[buf][kb8 + tg + 4][col];
            }
            #pragma unroll
            for (int mt = 0; mt < 4; mt++)
                #pragma unroll
                for (int nt = 0; nt < 4; nt++)
                    mma_tf32(acc[mt][nt], af[mt], bf[nt]);
        }
        __syncthreads();
    }

    float* sb = g_s + (size_t)b * N_ * N_;
    #pragma unroll
    for (int mt = 0; mt < 4; mt++) {
        #pragma unroll
        for (int nt = 0; nt < 4; nt++) {
            int row = i0 + wm * 64 + mt * 16 + g;
            int col = j0 + wn * 32 + nt * 8 + tg * 2;
            float2 v0 = {acc[mt][nt][0] * 0.0625f, acc[mt][nt][1] * 0.0625f};
            float2 v1 = {acc[mt][nt][2] * 0.0625f, acc[mt][nt][3] * 0.0625f};
            *reinterpret_cast<float2*>(&sb[(size_t)row * N_ + col]) = v0;
            *reinterpret_cast<float2*>(&sb[(size_t)(row + 8) * N_ + col]) = v1;
        }
    }
}

// ---------------------------------------------------------------------------
// Kernel 3a: partial column (over i) online max/sum-exp. float4 coalesced.
// grid (N/256, 8, B), block (64,4). Each block: 256 cols x 256-row slab.
// ---------------------------------------------------------------------------
__global__ __launch_bounds__(256) void colpart_kernel()
{
    const int jb = blockIdx.x, ip = blockIdx.y, b = blockIdx.z;
    const int tx = threadIdx.x, ty = threadIdx.y;
    const int j0 = jb * 256;
    const float* sb = g_s + (size_t)b * N_ * N_;

    float4 m4 = {-3.0e38f, -3.0e38f, -3.0e38f, -3.0e38f};
    float4 s4 = {0.0f, 0.0f, 0.0f, 0.0f};

    const int ibase = ip * 256;
    for (int i = ibase + ty; i < ibase + 256; i += 4) {
        float4 sv = *reinterpret_cast<const float4*>(&sb[(size_t)i * N_ + j0 + tx * 4]);
        float mn;
        mn = fmaxf(m4.x, sv.x); s4.x = s4.x * __expf(m4.x - mn) + __expf(sv.x - mn); m4.x = mn;
        mn = fmaxf(m4.y, sv.y); s4.y = s4.y * __expf(m4.y - mn) + __expf(sv.y - mn); m4.y = mn;
        mn = fmaxf(m4.z, sv.z); s4.z = s4.z * __expf(m4.z - mn) + __expf(sv.z - mn); m4.z = mn;
        mn = fmaxf(m4.w, sv.w); s4.w = s4.w * __expf(m4.w - mn) + __expf(sv.w - mn); m4.w = mn;
    }

    __shared__ float sm[4][256], ss[4][256];
    *reinterpret_cast<float4*>(&sm[ty][tx * 4]) = m4;
    *reinterpret_cast<float4*>(&ss[ty][tx * 4]) = s4;
    __syncthreads();

    if (ty == 0) {
        #pragma unroll
        for (int c = 0; c < 4; c++) {
            int j = tx * 4 + c;
            float M = sm[0][j], S = ss[0][j];
            #pragma unroll
            for (int r = 1; r < 4; r++) {
                float m2 = sm[r][j], s2 = ss[r][j];
                float mn = fmaxf(M, m2);
                S = S * __expf(M - mn) + s2 * __expf(m2 - mn);
                M = mn;
            }
            g_pmax[(b * 8 + ip) * N_ + j0 + j] = M;
            g_psum[(b * 8 + ip) * N_ + j0 + j] = S;
        }
    }
}

// ---------------------------------------------------------------------------
// Kernel 3b: combine 8 partials per column.
// grid (N/256, B), 256 thr.
// ---------------------------------------------------------------------------
__global__ __launch_bounds__(256) void colcomb_kernel()
{
    const int j = blockIdx.x * 256 + threadIdx.x;
    const int b = blockIdx.y;
    float M = -3.0e38f, S = 0.0f;
    #pragma unroll
    for (int p = 0; p < 8; p++) {
        float m2 = g_pmax[(b * 8 + p) * N_ + j];
        float s2 = g_psum[(b * 8 + p) * N_ + j];
        float mn = fmaxf(M, m2);
        S = S * __expf(M - mn) + s2 * __expf(m2 - mn);
        M = mn;
    }
    g_cmax[b * N_ + j] = M;
    g_csum[b * N_ + j] = S;
}

// ---------------------------------------------------------------------------
// Kernel 4 (tf32 MMA): ctx[b,c,j] = sum_i v[b,c,i] * P[b,i,j]
// ---------------------------------------------------------------------------
__global__ __launch_bounds__(256, 2) void ctx_mma()
{
    __shared__ __align__(16) float As[2][TBK][SSTRIDE];
    __shared__ __align__(16) float Bs[2][TBK][SSTRIDE];
    __shared__ float cmS[TBN], ciS[TBN];

    const int b  = blockIdx.z;
    const int c0 = blockIdx.y * TBM;
    const int j0 = blockIdx.x * TBN;
    const int tid  = threadIdx.x;
    const int lane = tid & 31, wid = tid >> 5;
    const int wm = wid & 1, wn = wid >> 1;
    const int g = lane >> 2, tg = lane & 3;

    const float* vb = g_v + (size_t)b * MID_ * N_;
    const float* sb = g_s + (size_t)b * N_ * N_;

    if (tid < TBN) {
        cmS[tid] = g_cmax[b * N_ + j0 + tid];
        ciS[tid] = 1.0f / g_csum[b * N_ + j0 + tid];
    }
    __syncthreads();

    float acc[4][4][4] = {};

    auto load_tile = [&](int buf, int k0) {
        #pragma unroll
        for (int r = 0; r < 2; r++) {
            int f = tid + r * 256;
            int c = f >> 2, q4 = (f & 3) << 2;
            float4 vv = *reinterpret_cast<const float4*>(&vb[(size_t)(c0 + c) * N_ + k0 + q4]);
            As[buf][q4 + 0][c] = vv.x;
            As[buf][q4 + 1][c] = vv.y;
            As[buf][q4 + 2][c] = vv.z;
            As[buf][q4 + 3][c] = vv.w;
        }
        #pragma unroll
        for (int r = 0; r < 2; r++) {
            int f  = tid + r * 256;
            int kk = f >> 5, j4 = (f & 31) << 2;
            float4 s4 = *reinterpret_cast<const float4*>(&sb[(size_t)(k0 + kk) * N_ + j0 + j4]);
            float4 p4;
            p4.x = __expf(s4.x - cmS[j4 + 0]) * ciS[j4 + 0];
            p4.y = __expf(s4.y - cmS[j4 + 1]) * ciS[j4 + 1];
            p4.z = __expf(s4.z - cmS[j4 + 2]) * ciS[j4 + 2];
            p4.w = __expf(s4.w - cmS[j4 + 3]) * ciS[j4 + 3];
            *reinterpret_cast<float4*>(&Bs[buf][kk][j4]) = p4;
        }
    };

    load_tile(0, 0);
    __syncthreads();

    for (int k0 = 0; k0 < N_; k0 += TBK) {
        const int buf = (k0 / TBK) & 1;
        if (k0 + TBK < N_) load_tile(buf ^ 1, k0 + TBK);

        #pragma unroll
        for (int ks = 0; ks < TBK / 8; ks++) {
            const int kb8 = ks * 8;
            float af[4][4], bf[4][2];
            #pragma unroll
            for (int mt = 0; mt < 4; mt++) {
                int row = wm * 64 + mt * 16 + g;
                af[mt][0] = As[buf][kb8 + tg][row];
                af[mt][1] = As[buf][kb8 + tg][row + 8];
                af[mt][2] = As[buf][kb8 + tg + 4][row];
                af[mt][3] = As[buf][kb8 + tg + 4][row + 8];
            }
            #pragma unroll
            for (int nt = 0; nt < 4; nt++) {
                int col = wn * 32 + nt * 8 + g;
                bf[nt][0] = Bs[buf][kb8 + tg][col];
                bf[nt][1] = Bs[buf][kb8 + tg + 4][col];
            }
            #pragma unroll
            for (int mt = 0; mt < 4; mt++)
                #pragma unroll
                for (int nt = 0; nt < 4; nt++)
                    mma_tf32(acc[mt][nt], af[mt], bf[nt]);
        }
        __syncthreads();
    }

    #pragma unroll
    for (int mt = 0; mt < 4; mt++) {
        #pragma unroll
        for (int nt = 0; nt < 4; nt++) {
            int row = c0 + wm * 64 + mt * 16 + g;
            int col = j0 + wn * 32 + nt * 8 + tg * 2;
            float2 v0 = {acc[mt][nt][0], acc[mt][nt][1]};
            float2 v1 = {acc[mt][nt][2], acc[mt][nt][3]};
            *reinterpret_cast<float2*>(&g_ctx[((size_t)b * MID_ + row) * N_ + col]) = v0;
            *reinterpret_cast<float2*>(&g_ctx[((size_t)b * MID_ + row + 8) * N_ + col]) = v1;
        }
    }
}

// ---------------------------------------------------------------------------
// Kernel 5 (tf32 MMA): out[b,c,n] = x + wo[c,m] @ ctx[b,m,n] + bo[c]
// grid (N/128, C/128, B), 256 thr.
// ---------------------------------------------------------------------------
__global__ __launch_bounds__(256, 2) void out_mma(
    const float* __restrict__ x,
    const float* __restrict__ wo,
    const float* __restrict__ bo,
    float* __restrict__ out)
{
    __shared__ __align__(16) float As[2][TBK][SSTRIDE];   // wo^T tile [k][c]
    __shared__ __align__(16) float Bs[2][TBK][SSTRIDE];   // ctx tile [k][n]

    const int b  = blockIdx.z;
    const int m0 = blockIdx.y * TBM;   // over C
    const int n0 = blockIdx.x * TBN;
    const int tid  = threadIdx.x;
    const int lane = tid & 31, wid = tid >> 5;
    const int wm = wid & 1, wn = wid >> 1;
    const int g = lane >> 2, tg = lane & 3;

    float acc[4][4][4] = {};

    auto load_tile = [&](int buf, int k0) {
        #pragma unroll
        for (int r = 0; r < 2; r++) {
            int f = tid + r * 256;
            int m = f >> 2, kq = (f & 3) << 2;
            float4 w4 = *reinterpret_cast<const float4*>(&wo[(size_t)(m0 + m) * MID_ + k0 + kq]);
            As[buf][kq + 0][m] = w4.x;
            As[buf][kq + 1][m] = w4.y;
            As[buf][kq + 2][m] = w4.z;
            As[buf][kq + 3][m] = w4.w;
        }
        #pragma unroll
        for (int r = 0; r < 2; r++) {
            int f  = tid + r * 256;
            int kk = f >> 5, n4 = (f & 31) << 2;
            *reinterpret_cast<float4*>(&Bs[buf][kk][n4]) =
                *reinterpret_cast<const float4*>(&g_ctx[((size_t)b * MID_ + k0 + kk) * N_ + n0 + n4]);
        }
    };

    load_tile(0, 0);
    __syncthreads();

    for (int k0 = 0; k0 < MID_; k0 += TBK) {
        const int buf = (k0 / TBK) & 1;
        if (k0 + TBK < MID_) load_tile(buf ^ 1, k0 + TBK);

        #pragma unroll
        for (int ks = 0; ks < TBK / 8; ks++) {
            const int kb8 = ks * 8;
            float af[4][4], bf[4][2];
            #pragma unroll
            for (int mt = 0; mt < 4; mt++) {
                int row = wm * 64 + mt * 16 + g;
                af[mt][0] = As[buf][kb8 + tg][row];
                af[mt][1] = As[buf][kb8 + tg][row + 8];
                af[mt][2] = As[buf][kb8 + tg + 4][row];
                af[mt][3] = As[buf][kb8 + tg + 4][row + 8];
            }
            #pragma unroll
            for (int nt = 0; nt < 4; nt++) {
                int col = wn * 32 + nt * 8 + g;
                bf[nt][0] = Bs[buf][kb8 + tg][col];
                bf[nt][1] = Bs[buf][kb8 + tg + 4][col];
            }
            #pragma unroll
            for (int mt = 0; mt < 4; mt++)
                #pragma unroll
                for (int nt = 0; nt < 4; nt++)
                    mma_tf32(acc[mt][nt], af[mt], bf[nt]);
        }
        __syncthreads();
    }

    #pragma unroll
    for (int mt = 0; mt < 4; mt++) {
        int r0 = m0 + wm * 64 + mt * 16 + g;
        int r1 = r0 + 8;
        float bo0 = bo[r0], bo1 = bo[r1];
        #pragma unroll
        for (int nt = 0; nt < 4; nt++) {
            int col = n0 + wn * 32 + nt * 8 + tg * 2;
            size_t a0 = ((size_t)b * C_ + r0) * N_ + col;
            size_t a1 = ((size_t)b * C_ + r1) * N_ + col;
            float2 x0 = *reinterpret_cast<const float2*>(&x[a0]);
            float2 x1 = *reinterpret_cast<const float2*>(&x[a1]);
            float2 v0 = {acc[mt][nt][0] + bo0 + x0.x, acc[mt][nt][1] + bo0 + x0.y};
            float2 v1 = {acc[mt][nt][2] + bo1 + x1.x, acc[mt][nt][3] + bo1 + x1.y};
            *reinterpret_cast<float2*>(&out[a0]) = v0;
            *reinterpret_cast<float2*>(&out[a1]) = v1;
        }
    }
}

// ---------------------------------------------------------------------------
extern "C" void kernel_launch(void* const* d_in, const int* in_sizes, int n_in,
                              void* d_out, int out_size)
{
    (void)in_sizes; (void)n_in; (void)out_size;
    const float* x     = (const float*)d_in[0];
    const float* wq    = (const float*)d_in[1];
    const float* bq    = (const float*)d_in[2];
    const float* gq    = (const float*)d_in[3];
    const float* betaq = (const float*)d_in[4];
    const float* wk    = (const float*)d_in[5];
    const float* bk    = (const float*)d_in[6];
    const float* gk    = (const float*)d_in[7];
    const float* betak = (const float*)d_in[8];
    const float* wv    = (const float*)d_in[9];
    const float* bv    = (const float*)d_in[10];
    const float* wo    = (const float*)d_in[11];
    const float* bo    = (const float*)d_in[12];
    const float* mq    = (const float*)d_in[13];
    const float* vq    = (const float*)d_in[14];
    const float* mk    = (const float*)d_in[15];
    const float* vk    = (const float*)d_in[16];
    float* out = (float*)d_out;

    dim3 blk(256);
    proj_mma<<<dim3(N_/TBN, MID_/TBM, 3*B_), blk>>>(
        x, wq, bq, gq, betaq, mq, vq, wk, bk, gk, betak, mk, vk, wv, bv);
    scores_mma<<<dim3(N_/TBN, N_/TBM, B_), blk>>>();
    colpart_kernel<<<dim3(N_/256, 8, B_), dim3(64, 4)>>>();
    colcomb_kernel<<<dim3(N_/256, B_), blk>>>();
    ctx_mma<<<dim3(N_/TBN, MID_/TBM, B_), blk>>>();
    out_mma<<<dim3(N_/TBN, C_/TBM, B_), blk>>>(x, wo, bo, out);
}

// round 5
// speedup vs baseline: 4.1491x; 1.5236x over previous
#include <cuda_runtime.h>
#include <cuda_bf16.h>
#include <math.h>

// Problem constants
constexpr int B_   = 16;
constexpr int C_   = 512;
constexpr int MID_ = 256;
constexpr int N_   = 2048;
constexpr float EPS_ = 1e-5f;

// MMA tiling
constexpr int TBM = 128;   // m-dim tile (rows of D)
constexpr int TBN = 128;   // n-dim tile (cols of D)
constexpr int TBK = 32;    // k per smem tile
constexpr int TSTR = 40;   // bf16 row stride (80B): 20 words -> frag LDS conflict-free

typedef __nv_bfloat16 bf16;
typedef __nv_bfloat162 bf162;

// Scratch
__device__ bf16 g_qT[(size_t)B_ * N_ * MID_];   // q^T: [b][n][mid]
__device__ bf16 g_kT[(size_t)B_ * N_ * MID_];   // k^T: [b][n][mid]
__device__ bf16 g_v [(size_t)B_ * MID_ * N_];   // v:   [b][mid][n]
__device__ bf16 g_sT[(size_t)B_ * N_ * N_];     // S^T: [b][j][i]
__device__ bf16 g_ctxT[(size_t)B_ * N_ * MID_]; // ctx^T: [b][n][mid]
__device__ float g_cmax[B_ * N_];
__device__ float g_cinv[B_ * N_];

__device__ __forceinline__ unsigned pack2(float lo, float hi) {
    bf162 h = __floats2bfloat162_rn(lo, hi);
    return *reinterpret_cast<unsigned*>(&h);
}

// ---------------------------------------------------------------------------
// bf16 warp MMA: D(16x8) += A(16x16,row) * B(16x8,col)
// ---------------------------------------------------------------------------
__device__ __forceinline__ void mma_bf16(float c[4], const unsigned a[4], const unsigned b[2])
{
    asm volatile(
        "mma.sync.aligned.m16n8k16.row.col.f32.bf16.bf16.f32 "
        "{%0,%1,%2,%3}, {%4,%5,%6,%7}, {%8,%9}, {%0,%1,%2,%3};\n"
        : "+f"(c[0]), "+f"(c[1]), "+f"(c[2]), "+f"(c[3])
        : "r"(a[0]), "r"(a[1]), "r"(a[2]), "r"(a[3]),
          "r"(b[0]), "r"(b[1]));
}

// Shared k-loop step over one TBK=32 tile pair (2 ksteps of 16).
// TA: [128][TSTR] (m rows), TB: [128][TSTR] (n rows). acc[4 mt][4 nt][4].
__device__ __forceinline__ void mma_tile(const bf16* TA, const bf16* TB,
                                         float acc[4][4][4],
                                         int wm, int wn, int g, int tg)
{
    #pragma unroll
    for (int ks = 0; ks < 2; ks++) {
        const int kb = ks * 16 + 2 * tg;
        unsigned af[4][4], bfr[4][2];
        #pragma unroll
        for (int mt = 0; mt < 4; mt++) {
            int row = wm * 64 + mt * 16 + g;
            af[mt][0] = *reinterpret_cast<const unsigned*>(&TA[row * TSTR + kb]);
            af[mt][1] = *reinterpret_cast<const unsigned*>(&TA[(row + 8) * TSTR + kb]);
            af[mt][2] = *reinterpret_cast<const unsigned*>(&TA[row * TSTR + kb + 8]);
            af[mt][3] = *reinterpret_cast<const unsigned*>(&TA[(row + 8) * TSTR + kb + 8]);
        }
        #pragma unroll
        for (int nt = 0; nt < 4; nt++) {
            int col = wn * 32 + nt * 8 + g;
            bfr[nt][0] = *reinterpret_cast<const unsigned*>(&TB[col * TSTR + kb]);
            bfr[nt][1] = *reinterpret_cast<const unsigned*>(&TB[col * TSTR + kb + 8]);
        }
        #pragma unroll
        for (int mt = 0; mt < 4; mt++)
            #pragma unroll
            for (int nt = 0; nt < 4; nt++)
                mma_bf16(acc[mt][nt], af[mt], bfr[nt]);
    }
}

// Stage: direct bf16 copy, global rows [row][k-contig] (stride gstride) -> tile.
__device__ __forceinline__ void stage_bf16(bf16* T, const bf16* src, size_t gstride,
                                           int k0, int tid)
{
    #pragma unroll
    for (int r = 0; r < 2; r++) {
        int f = tid + r * 256;
        int row = f >> 2, k8 = (f & 3) * 8;
        *reinterpret_cast<uint4*>(&T[row * TSTR + k8]) =
            *reinterpret_cast<const uint4*>(&src[(size_t)row * gstride + k0 + k8]);
    }
}

// Stage: fp32 global rows [row][k-contig] -> bf16 tile.
__device__ __forceinline__ void stage_f32(bf16* T, const float* src, size_t gstride,
                                          int k0, int tid)
{
    #pragma unroll
    for (int r = 0; r < 4; r++) {
        int f = tid + r * 256;
        int row = f >> 3, k4 = (f & 7) * 4;
        float4 w4 = *reinterpret_cast<const float4*>(&src[(size_t)row * gstride + k0 + k4]);
        uint2 p;
        p.x = pack2(w4.x, w4.y);
        p.y = pack2(w4.z, w4.w);
        *reinterpret_cast<uint2*>(&T[row * TSTR + k4]) = p;
    }
}

// Stage: x transpose: fp32 global [c][n] -> tile [n][c] bf16.
__device__ __forceinline__ void stage_xT(bf16* T, const float* xb, int k0, int n0, int tid)
{
    #pragma unroll
    for (int r = 0; r < 16; r++) {
        int f = tid + r * 256;
        int c = f >> 7, n = f & 127;
        T[n * TSTR + c] = __float2bfloat16(xb[(size_t)(k0 + c) * N_ + n0 + n]);
    }
}

// ---------------------------------------------------------------------------
// projT: q/k projection, transposed output. D[n][mid] = sum_c x[c][n] w[mid][c]
//   A = x^T tile [n][c] (transpose-staged), B = w tile [mid][c] (direct)
//   epilogue: BN+ReLU per mid (column), write g_qT/g_kT [b][n][mid] bf16.
// grid (MID/128=2, N/128=16, 2B), 256 thr.
// ---------------------------------------------------------------------------
__global__ __launch_bounds__(256, 2) void projT_mma(
    const float* __restrict__ x,
    const float* __restrict__ wq, const float* __restrict__ bq,
    const float* __restrict__ gq, const float* __restrict__ betaq,
    const float* __restrict__ mq, const float* __restrict__ vq,
    const float* __restrict__ wk, const float* __restrict__ bk,
    const float* __restrict__ gk, const float* __restrict__ betak,
    const float* __restrict__ mk, const float* __restrict__ vk)
{
    __shared__ __align__(16) bf16 As[2][TBM * TSTR];
    __shared__ __align__(16) bf16 Bs[2][TBM * TSTR];

    const int mat = blockIdx.z / B_;
    const int b   = blockIdx.z % B_;
    const int n0  = blockIdx.y * TBM;    // over N (m-dim)
    const int c0  = blockIdx.x * TBN;    // over MID (n-dim)
    const int tid  = threadIdx.x;
    const int lane = tid & 31, wid = tid >> 5;
    const int wm = wid & 1, wn = wid >> 1;
    const int g = lane >> 2, tg = lane & 3;

    const float* w  = (mat == 0) ? wq : wk;
    const float* xb = x + (size_t)b * C_ * N_;

    float acc[4][4][4] = {};

    stage_xT(As[0], xb, 0, n0, tid);
    stage_f32(Bs[0], w + (size_t)c0 * C_, C_, 0, tid);
    __syncthreads();

    for (int k0 = 0; k0 < C_; k0 += TBK) {
        const int buf = (k0 / TBK) & 1;
        if (k0 + TBK < C_) {
            stage_xT(As[buf ^ 1], xb, k0 + TBK, n0, tid);
            stage_f32(Bs[buf ^ 1], w + (size_t)c0 * C_, C_, k0 + TBK, tid);
        }
        mma_tile(As[buf], Bs[buf], acc, wm, wn, g, tg);
        __syncthreads();
    }

    bf16* dst = (mat == 0) ? g_qT : g_kT;
    const float *gb = (mat == 0) ? gq : gk, *bb = (mat == 0) ? bq : bk;
    const float *mb = (mat == 0) ? mq : mk, *vb2 = (mat == 0) ? vq : vk;
    const float *eb = (mat == 0) ? betaq : betak;

    // channel params per (nt, half): col = c0 + wn*32 + nt*8 + 2tg + {0,1}
    float sc[4][2], of[4][2];
    #pragma unroll
    for (int nt = 0; nt < 4; nt++) {
        #pragma unroll
        for (int h = 0; h < 2; h++) {
            int ch = c0 + wn * 32 + nt * 8 + 2 * tg + h;
            float inv = gb[ch] * rsqrtf(vb2[ch] + EPS_);
            sc[nt][h] = inv;
            of[nt][h] = (bb[ch] - mb[ch]) * inv + eb[ch];
        }
    }

    #pragma unroll
    for (int mt = 0; mt < 4; mt++) {
        int r0 = n0 + wm * 64 + mt * 16 + g;
        #pragma unroll
        for (int nt = 0; nt < 4; nt++) {
            int col = c0 + wn * 32 + nt * 8 + 2 * tg;
            float v00 = fmaxf(acc[mt][nt][0] * sc[nt][0] + of[nt][0], 0.0f);
            float v01 = fmaxf(acc[mt][nt][1] * sc[nt][1] + of[nt][1], 0.0f);
            float v10 = fmaxf(acc[mt][nt][2] * sc[nt][0] + of[nt][0], 0.0f);
            float v11 = fmaxf(acc[mt][nt][3] * sc[nt][1] + of[nt][1], 0.0f);
            *reinterpret_cast<unsigned*>(&dst[((size_t)b * N_ + r0) * MID_ + col]) = pack2(v00, v01);
            *reinterpret_cast<unsigned*>(&dst[((size_t)b * N_ + r0 + 8) * MID_ + col]) = pack2(v10, v11);
        }
    }
}

// ---------------------------------------------------------------------------
// projV: v projection, plain layout. D[mid][n] = sum_c w[mid][c] x[c][n]
//   A = w tile [mid][c] direct, B = x^T tile [n][c] transpose-staged.
// grid (N/128=16, MID/128=2, B), 256 thr.
// ---------------------------------------------------------------------------
__global__ __launch_bounds__(256, 2) void projV_mma(
    const float* __restrict__ x,
    const float* __restrict__ wv, const float* __restrict__ bv)
{
    __shared__ __align__(16) bf16 As[2][TBM * TSTR];
    __shared__ __align__(16) bf16 Bs[2][TBM * TSTR];

    const int b  = blockIdx.z;
    const int m0 = blockIdx.y * TBM;    // over MID
    const int n0 = blockIdx.x * TBN;    // over N
    const int tid  = threadIdx.x;
    const int lane = tid & 31, wid = tid >> 5;
    const int wm = wid & 1, wn = wid >> 1;
    const int g = lane >> 2, tg = lane & 3;

    const float* xb = x + (size_t)b * C_ * N_;

    float acc[4][4][4] = {};

    stage_f32(As[0], wv + (size_t)m0 * C_, C_, 0, tid);
    stage_xT(Bs[0], xb, 0, n0, tid);
    __syncthreads();

    for (int k0 = 0; k0 < C_; k0 += TBK) {
        const int buf = (k0 / TBK) & 1;
        if (k0 + TBK < C_) {
            stage_f32(As[buf ^ 1], wv + (size_t)m0 * C_, C_, k0 + TBK, tid);
            stage_xT(Bs[buf ^ 1], xb, k0 + TBK, n0, tid);
        }
        mma_tile(As[buf], Bs[buf], acc, wm, wn, g, tg);
        __syncthreads();
    }

    #pragma unroll
    for (int mt = 0; mt < 4; mt++) {
        int r0 = m0 + wm * 64 + mt * 16 + g;
        int r1 = r0 + 8;
        float b0v = bv[r0], b1v = bv[r1];
        #pragma unroll
        for (int nt = 0; nt < 4; nt++) {
            int col = n0 + wn * 32 + nt * 8 + 2 * tg;
            *reinterpret_cast<unsigned*>(&g_v[((size_t)b * MID_ + r0) * N_ + col]) =
                pack2(acc[mt][nt][0] + b0v, acc[mt][nt][1] + b0v);
            *reinterpret_cast<unsigned*>(&g_v[((size_t)b * MID_ + r1) * N_ + col]) =
                pack2(acc[mt][nt][2] + b1v, acc[mt][nt][3] + b1v);
        }
    }
}

// ---------------------------------------------------------------------------
// scores: S^T[j][i] = (1/16) sum_m k[m][j] q[m][i]
//   A = g_kT tile [j][m] direct, B = g_qT tile [i][m] direct.
// grid (N/128 i, N/128 j, B), 256 thr.
// ---------------------------------------------------------------------------
__global__ __launch_bounds__(256, 2) void scores_mma()
{
    __shared__ __align__(16) bf16 As[2][TBM * TSTR];
    __shared__ __align__(16) bf16 Bs[2][TBM * TSTR];

    const int b  = blockIdx.z;
    const int j0 = blockIdx.y * TBM;
    const int i0 = blockIdx.x * TBN;
    const int tid  = threadIdx.x;
    const int lane = tid & 31, wid = tid >> 5;
    const int wm = wid & 1, wn = wid >> 1;
    const int g = lane >> 2, tg = lane & 3;

    const bf16* kT = g_kT + ((size_t)b * N_ + j0) * MID_;
    const bf16* qT = g_qT + ((size_t)b * N_ + i0) * MID_;

    float acc[4][4][4] = {};

    stage_bf16(As[0], kT, MID_, 0, tid);
    stage_bf16(Bs[0], qT, MID_, 0, tid);
    __syncthreads();

    for (int k0 = 0; k0 < MID_; k0 += TBK) {
        const int buf = (k0 / TBK) & 1;
        if (k0 + TBK < MID_) {
            stage_bf16(As[buf ^ 1], kT, MID_, k0 + TBK, tid);
            stage_bf16(Bs[buf ^ 1], qT, MID_, k0 + TBK, tid);
        }
        mma_tile(As[buf], Bs[buf], acc, wm, wn, g, tg);
        __syncthreads();
    }

    #pragma unroll
    for (int mt = 0; mt < 4; mt++) {
        int row = j0 + wm * 64 + mt * 16 + g;
        #pragma unroll
        for (int nt = 0; nt < 4; nt++) {
            int col = i0 + wn * 32 + nt * 8 + 2 * tg;
            *reinterpret_cast<unsigned*>(&g_sT[((size_t)b * N_ + row) * N_ + col]) =
                pack2(acc[mt][nt][0] * 0.0625f, acc[mt][nt][1] * 0.0625f);
            *reinterpret_cast<unsigned*>(&g_sT[((size_t)b * N_ + row + 8) * N_ + col]) =
                pack2(acc[mt][nt][2] * 0.0625f, acc[mt][nt][3] * 0.0625f);
        }
    }
}

// ---------------------------------------------------------------------------
// colreduce: per j, online max/sum-exp over i (S^T row). One warp per row.
// grid (N/8, B), 256 thr.
// ---------------------------------------------------------------------------
__global__ __launch_bounds__(256) void colreduce_kernel()
{
    const int b = blockIdx.y;
    const int w = threadIdx.x >> 5, lane = threadIdx.x & 31;
    const int j = blockIdx.x * 8 + w;
    const uint4* row = reinterpret_cast<const uint4*>(g_sT + ((size_t)b * N_ + j) * N_);

    float M = -3.0e38f, S = 0.0f;
    #pragma unroll
    for (int it = 0; it < 8; it++) {
        uint4 rv = row[lane + 32 * it];
        const unsigned u[4] = {rv.x, rv.y, rv.z, rv.w};
        #pragma unroll
        for (int q = 0; q < 4; q++) {
            float2 f = __bfloat1622float2(*reinterpret_cast<const bf162*>(&u[q]));
            float mn = fmaxf(M, f.x);
            S = S * __expf(M - mn) + __expf(f.x - mn); M = mn;
            mn = fmaxf(M, f.y);
            S = S * __expf(M - mn) + __expf(f.y - mn); M = mn;
        }
    }
    #pragma unroll
    for (int off = 16; off > 0; off >>= 1) {
        float om = __shfl_xor_sync(0xffffffffu, M, off);
        float os = __shfl_xor_sync(0xffffffffu, S, off);
        float mn = fmaxf(M, om);
        S = S * __expf(M - mn) + os * __expf(om - mn);
        M = mn;
    }
    if (lane == 0) {
        g_cmax[b * N_ + j] = M;
        g_cinv[b * N_ + j] = 1.0f / S;
    }
}

// ---------------------------------------------------------------------------
// ctx: ctx^T[j][c] = sum_i P[i][j] v[c][i],  P = exp(S^T[j][i]-cm[j])*ci[j]
//   A = P tile [j][i] (exp fused in staging), B = v tile [c][i] direct.
// grid (MID/128=2, N/128=16, B), 256 thr.
// ---------------------------------------------------------------------------
__global__ __launch_bounds__(256, 2) void ctx_mma()
{
    __shared__ __align__(16) bf16 As[2][TBM * TSTR];
    __shared__ __align__(16) bf16 Bs[2][TBM * TSTR];
    __shared__ float cmS[TBM], ciS[TBM];

    const int b  = blockIdx.z;
    const int j0 = blockIdx.y * TBM;    // m-dim over N
    const int c0 = blockIdx.x * TBN;    // n-dim over MID
    const int tid  = threadIdx.x;
    const int lane = tid & 31, wid = tid >> 5;
    const int wm = wid & 1, wn = wid >> 1;
    const int g = lane >> 2, tg = lane & 3;

    if (tid < TBM) {
        cmS[tid] = g_cmax[b * N_ + j0 + tid];
        ciS[tid] = g_cinv[b * N_ + j0 + tid];
    }
    __syncthreads();

    const bf16* sT = g_sT + ((size_t)b * N_ + j0) * N_;
    const bf16* vb = g_v + ((size_t)b * MID_ + c0) * N_;

    float acc[4][4][4] = {};

    auto stage_P = [&](bf16* T, int k0) {
        #pragma unroll
        for (int r = 0; r < 2; r++) {
            int f = tid + r * 256;
            int j = f >> 2, i8 = (f & 3) * 8;
            uint4 raw = *reinterpret_cast<const uint4*>(&sT[(size_t)j * N_ + k0 + i8]);
            const unsigned u[4] = {raw.x, raw.y, raw.z, raw.w};
            float cm = cmS[j], ci = ciS[j];
            uint4 outp;
            unsigned po[4];
            #pragma unroll
            for (int q = 0; q < 4; q++) {
                float2 fv = __bfloat1622float2(*reinterpret_cast<const bf162*>(&u[q]));
                po[q] = pack2(__expf(fv.x - cm) * ci, __expf(fv.y - cm) * ci);
            }
            outp.x = po[0]; outp.y = po[1]; outp.z = po[2]; outp.w = po[3];
            *reinterpret_cast<uint4*>(&T[j * TSTR + i8]) = outp;
        }
    };

    stage_P(As[0], 0);
    stage_bf16(Bs[0], vb, N_, 0, tid);
    __syncthreads();

    for (int k0 = 0; k0 < N_; k0 += TBK) {
        const int buf = (k0 / TBK) & 1;
        if (k0 + TBK < N_) {
            stage_P(As[buf ^ 1], k0 + TBK);
            stage_bf16(Bs[buf ^ 1], vb, N_, k0 + TBK, tid);
        }
        mma_tile(As[buf], Bs[buf], acc, wm, wn, g, tg);
        __syncthreads();
    }

    #pragma unroll
    for (int mt = 0; mt < 4; mt++) {
        int row = j0 + wm * 64 + mt * 16 + g;
        #pragma unroll
        for (int nt = 0; nt < 4; nt++) {
            int col = c0 + wn * 32 + nt * 8 + 2 * tg;
            *reinterpret_cast<unsigned*>(&g_ctxT[((size_t)b * N_ + row) * MID_ + col]) =
                pack2(acc[mt][nt][0], acc[mt][nt][1]);
            *reinterpret_cast<unsigned*>(&g_ctxT[((size_t)b * N_ + row + 8) * MID_ + col]) =
                pack2(acc[mt][nt][2], acc[mt][nt][3]);
        }
    }
}

// ---------------------------------------------------------------------------
// out: out[c'][n] = x + sum_m wo[c'][m] ctx^T[n][m] + bo[c']
//   A = wo tile [c'][m] direct fp32->bf16, B = g_ctxT tile [n][m] direct.
// grid (N/128=16, C/128=4, B), 256 thr.
// ---------------------------------------------------------------------------
__global__ __launch_bounds__(256, 2) void out_mma(
    const float* __restrict__ x,
    const float* __restrict__ wo,
    const float* __restrict__ bo,
    float* __restrict__ out)
{
    __shared__ __align__(16) bf16 As[2][TBM * TSTR];
    __shared__ __align__(16) bf16 Bs[2][TBM * TSTR];

    const int b  = blockIdx.z;
    const int m0 = blockIdx.y * TBM;    // over C
    const int n0 = blockIdx.x * TBN;    // over N
    const int tid  = threadIdx.x;
    const int lane = tid & 31, wid = tid >> 5;
    const int wm = wid & 1, wn = wid >> 1;
    const int g = lane >> 2, tg = lane & 3;

    const bf16* cT = g_ctxT + ((size_t)b * N_ + n0) * MID_;

    float acc[4][4][4] = {};

    stage_f32(As[0], wo + (size_t)m0 * MID_, MID_, 0, tid);
    stage_bf16(Bs[0], cT, MID_, 0, tid);
    __syncthreads();

    for (int k0 = 0; k0 < MID_; k0 += TBK) {
        const int buf = (k0 / TBK) & 1;
        if (k0 + TBK < MID_) {
            stage_f32(As[buf ^ 1], wo + (size_t)m0 * MID_, MID_, k0 + TBK, tid);
            stage_bf16(Bs[buf ^ 1], cT, MID_, k0 + TBK, tid);
        }
        mma_tile(As[buf], Bs[buf], acc, wm, wn, g, tg);
        __syncthreads();
    }

    #pragma unroll
    for (int mt = 0; mt < 4; mt++) {
        int r0 = m0 + wm * 64 + mt * 16 + g;
        int r1 = r0 + 8;
        float bo0 = bo[r0], bo1 = bo[r1];
        #pragma unroll
        for (int nt = 0; nt < 4; nt++) {
            int col = n0 + wn * 32 + nt * 8 + 2 * tg;
            size_t a0 = ((size_t)b * C_ + r0) * N_ + col;
            size_t a1 = ((size_t)b * C_ + r1) * N_ + col;
            float2 x0 = *reinterpret_cast<const float2*>(&x[a0]);
            float2 x1 = *reinterpret_cast<const float2*>(&x[a1]);
            float2 v0 = {acc[mt][nt][0] + bo0 + x0.x, acc[mt][nt][1] + bo0 + x0.y};
            float2 v1 = {acc[mt][nt][2] + bo1 + x1.x, acc[mt][nt][3] + bo1 + x1.y};
            *reinterpret_cast<float2*>(&out[a0]) = v0;
            *reinterpret_cast<float2*>(&out[a1]) = v1;
        }
    }
}

// ---------------------------------------------------------------------------
extern "C" void kernel_launch(void* const* d_in, const int* in_sizes, int n_in,
                              void* d_out, int out_size)
{
    (void)in_sizes; (void)n_in; (void)out_size;
    const float* x     = (const float*)d_in[0];
    const float* wq    = (const float*)d_in[1];
    const float* bq    = (const float*)d_in[2];
    const float* gq    = (const float*)d_in[3];
    const float* betaq = (const float*)d_in[4];
    const float* wk    = (const float*)d_in[5];
    const float* bk    = (const float*)d_in[6];
    const float* gk    = (const float*)d_in[7];
    const float* betak = (const float*)d_in[8];
    const float* wv    = (const float*)d_in[9];
    const float* bv    = (const float*)d_in[10];
    const float* wo    = (const float*)d_in[11];
    const float* bo    = (const float*)d_in[12];
    const float* mq    = (const float*)d_in[13];
    const float* vq    = (const float*)d_in[14];
    const float* mk    = (const float*)d_in[15];
    const float* vk    = (const float*)d_in[16];
    float* out = (float*)d_out;

    dim3 blk(256);
    projT_mma<<<dim3(MID_/TBN, N_/TBM, 2*B_), blk>>>(
        x, wq, bq, gq, betaq, mq, vq, wk, bk, gk, betak, mk, vk);
    projV_mma<<<dim3(N_/TBN, MID_/TBM, B_), blk>>>(x, wv, bv);
    scores_mma<<<dim3(N_/TBN, N_/TBM, B_), blk>>>();
    colreduce_kernel<<<dim3(N_/8, B_), blk>>>();
    ctx_mma<<<dim3(MID_/TBN, N_/TBM, B_), blk>>>();
    out_mma<<<dim3(N_/TBN, C_/TBM, B_), blk>>>(x, wo, bo, out);
}

// round 6
// speedup vs baseline: 4.2799x; 1.0315x over previous
#include <cuda_runtime.h>
#include <cuda_bf16.h>
#include <math.h>

// Problem constants
constexpr int B_   = 16;
constexpr int C_   = 512;
constexpr int MID_ = 256;
constexpr int N_   = 2048;
constexpr float EPS_ = 1e-5f;

// MMA tiling
constexpr int TBM = 128;   // m-dim tile (rows of D)
constexpr int TBN = 128;   // n-dim tile (cols of D)
constexpr int TBK = 32;    // k per smem tile
constexpr int TSTR = 40;   // bf16 row stride (80B): 20 words -> ldmatrix conflict-free

typedef __nv_bfloat16 bf16;
typedef __nv_bfloat162 bf162;

// Scratch
__device__ bf16 g_qT[(size_t)B_ * N_ * MID_];   // q^T: [b][n][mid]
__device__ bf16 g_kT[(size_t)B_ * N_ * MID_];   // k^T: [b][n][mid]
__device__ bf16 g_v [(size_t)B_ * MID_ * N_];   // v:   [b][mid][n]
__device__ bf16 g_sT[(size_t)B_ * N_ * N_];     // S^T: [b][j][i]
__device__ bf16 g_ctxT[(size_t)B_ * N_ * MID_]; // ctx^T: [b][n][mid]
__device__ float g_cmax[B_ * N_];
__device__ float g_cinv[B_ * N_];

__device__ __forceinline__ unsigned pack2(float lo, float hi) {
    bf162 h = __floats2bfloat162_rn(lo, hi);
    return *reinterpret_cast<unsigned*>(&h);
}

// ---------------------------------------------------------------------------
// bf16 warp MMA: D(16x8) += A(16x16,row) * B(16x8,col)
// ---------------------------------------------------------------------------
__device__ __forceinline__ void mma_bf16(float c[4], const unsigned a[4], const unsigned b[2])
{
    asm volatile(
        "mma.sync.aligned.m16n8k16.row.col.f32.bf16.bf16.f32 "
        "{%0,%1,%2,%3}, {%4,%5,%6,%7}, {%8,%9}, {%0,%1,%2,%3};\n"
        : "+f"(c[0]), "+f"(c[1]), "+f"(c[2]), "+f"(c[3])
        : "r"(a[0]), "r"(a[1]), "r"(a[2]), "r"(a[3]),
          "r"(b[0]), "r"(b[1]));
}

__device__ __forceinline__ void ldsm_x4(unsigned r[4], const bf16* p)
{
    unsigned addr = (unsigned)__cvta_generic_to_shared(p);
    asm volatile(
        "ldmatrix.sync.aligned.m8n8.x4.shared.b16 {%0,%1,%2,%3}, [%4];\n"
        : "=r"(r[0]), "=r"(r[1]), "=r"(r[2]), "=r"(r[3]) : "r"(addr));
}

// Shared k-loop step over one TBK=32 tile pair (2 ksteps of 16), ldmatrix frags.
// TA: [128][TSTR] (m rows), TB: [128][TSTR] (n rows). acc[4 mt][4 nt][4].
__device__ __forceinline__ void mma_tile(const bf16* TA, const bf16* TB,
                                         float acc[4][4][4],
                                         int wm, int wn, int lane)
{
    // A: lanes 0-7 rows 0-7 (k lo), 8-15 rows 8-15 (k lo), 16-23 rows 0-7 (k hi), 24-31 rows 8-15 (k hi)
    const int arow = (lane & 15);
    const int akof = (lane >> 4) << 3;        // 0 or 8
    // B: lanes 0-7 cols nt+0-7 (k lo), 8-15 same cols (k hi), 16-23 cols nt+8.. (k lo), 24-31 (k hi)
    const int bcol = (lane & 7) + ((lane >> 4) << 3);
    const int bkof = (lane & 8);              // 0 or 8

    #pragma unroll
    for (int ks = 0; ks < 2; ks++) {
        const int kb = ks * 16;
        unsigned af[4][4], bfr[4][2];
        #pragma unroll
        for (int mt = 0; mt < 4; mt++) {
            int row = wm * 64 + mt * 16 + arow;
            ldsm_x4(af[mt], &TA[row * TSTR + kb + akof]);
        }
        #pragma unroll
        for (int np = 0; np < 2; np++) {
            unsigned r4[4];
            int col = wn * 32 + np * 16 + bcol;
            ldsm_x4(r4, &TB[col * TSTR + kb + bkof]);
            bfr[np * 2][0]     = r4[0];
            bfr[np * 2][1]     = r4[1];
            bfr[np * 2 + 1][0] = r4[2];
            bfr[np * 2 + 1][1] = r4[3];
        }
        #pragma unroll
        for (int mt = 0; mt < 4; mt++)
            #pragma unroll
            for (int nt = 0; nt < 4; nt++)
                mma_bf16(acc[mt][nt], af[mt], bfr[nt]);
    }
}

// Stage: direct bf16 copy, global rows [row][k-contig] (stride gstride) -> tile.
__device__ __forceinline__ void stage_bf16(bf16* T, const bf16* src, size_t gstride,
                                           int k0, int tid)
{
    #pragma unroll
    for (int r = 0; r < 2; r++) {
        int f = tid + r * 256;
        int row = f >> 2, k8 = (f & 3) * 8;
        *reinterpret_cast<uint4*>(&T[row * TSTR + k8]) =
            *reinterpret_cast<const uint4*>(&src[(size_t)row * gstride + k0 + k8]);
    }
}

// Stage: fp32 global rows [row][k-contig] -> bf16 tile.
__device__ __forceinline__ void stage_f32(bf16* T, const float* src, size_t gstride,
                                          int k0, int tid)
{
    #pragma unroll
    for (int r = 0; r < 4; r++) {
        int f = tid + r * 256;
        int row = f >> 3, k4 = (f & 7) * 4;
        float4 w4 = *reinterpret_cast<const float4*>(&src[(size_t)row * gstride + k0 + k4]);
        uint2 p;
        p.x = pack2(w4.x, w4.y);
        p.y = pack2(w4.z, w4.w);
        *reinterpret_cast<uint2*>(&T[row * TSTR + k4]) = p;
    }
}

// Stage: x transpose: fp32 global [c][n] -> tile [n][c] bf16.
__device__ __forceinline__ void stage_xT(bf16* T, const float* xb, int k0, int n0, int tid)
{
    #pragma unroll
    for (int r = 0; r < 16; r++) {
        int f = tid + r * 256;
        int c = f >> 7, n = f & 127;
        T[n * TSTR + c] = __float2bfloat16(xb[(size_t)(k0 + c) * N_ + n0 + n]);
    }
}

// ---------------------------------------------------------------------------
// projT: q/k projection, transposed output. D[n][mid] = sum_c x[c][n] w[mid][c]
// grid (MID/128=2, N/128=16, 2B), 256 thr.
// ---------------------------------------------------------------------------
__global__ __launch_bounds__(256, 2) void projT_mma(
    const float* __restrict__ x,
    const float* __restrict__ wq, const float* __restrict__ bq,
    const float* __restrict__ gq, const float* __restrict__ betaq,
    const float* __restrict__ mq, const float* __restrict__ vq,
    const float* __restrict__ wk, const float* __restrict__ bk,
    const float* __restrict__ gk, const float* __restrict__ betak,
    const float* __restrict__ mk, const float* __restrict__ vk)
{
    __shared__ __align__(16) bf16 As[2][TBM * TSTR];
    __shared__ __align__(16) bf16 Bs[2][TBM * TSTR];

    const int mat = blockIdx.z / B_;
    const int b   = blockIdx.z % B_;
    const int n0  = blockIdx.y * TBM;
    const int c0  = blockIdx.x * TBN;
    const int tid  = threadIdx.x;
    const int lane = tid & 31, wid = tid >> 5;
    const int wm = wid & 1, wn = wid >> 1;
    const int g = lane >> 2, tg = lane & 3;

    const float* w  = (mat == 0) ? wq : wk;
    const float* xb = x + (size_t)b * C_ * N_;

    float acc[4][4][4] = {};

    stage_xT(As[0], xb, 0, n0, tid);
    stage_f32(Bs[0], w + (size_t)c0 * C_, C_, 0, tid);
    __syncthreads();

    for (int k0 = 0; k0 < C_; k0 += TBK) {
        const int buf = (k0 / TBK) & 1;
        if (k0 + TBK < C_) {
            stage_xT(As[buf ^ 1], xb, k0 + TBK, n0, tid);
            stage_f32(Bs[buf ^ 1], w + (size_t)c0 * C_, C_, k0 + TBK, tid);
        }
        mma_tile(As[buf], Bs[buf], acc, wm, wn, lane);
        __syncthreads();
    }

    bf16* dst = (mat == 0) ? g_qT : g_kT;
    const float *gb = (mat == 0) ? gq : gk, *bb = (mat == 0) ? bq : bk;
    const float *mb = (mat == 0) ? mq : mk, *vb2 = (mat == 0) ? vq : vk;
    const float *eb = (mat == 0) ? betaq : betak;

    float sc[4][2], of[4][2];
    #pragma unroll
    for (int nt = 0; nt < 4; nt++) {
        #pragma unroll
        for (int h = 0; h < 2; h++) {
            int ch = c0 + wn * 32 + nt * 8 + 2 * tg + h;
            float inv = gb[ch] * rsqrtf(vb2[ch] + EPS_);
            sc[nt][h] = inv;
            of[nt][h] = (bb[ch] - mb[ch]) * inv + eb[ch];
        }
    }

    #pragma unroll
    for (int mt = 0; mt < 4; mt++) {
        int r0 = n0 + wm * 64 + mt * 16 + g;
        #pragma unroll
        for (int nt = 0; nt < 4; nt++) {
            int col = c0 + wn * 32 + nt * 8 + 2 * tg;
            float v00 = fmaxf(acc[mt][nt][0] * sc[nt][0] + of[nt][0], 0.0f);
            float v01 = fmaxf(acc[mt][nt][1] * sc[nt][1] + of[nt][1], 0.0f);
            float v10 = fmaxf(acc[mt][nt][2] * sc[nt][0] + of[nt][0], 0.0f);
            float v11 = fmaxf(acc[mt][nt][3] * sc[nt][1] + of[nt][1], 0.0f);
            *reinterpret_cast<unsigned*>(&dst[((size_t)b * N_ + r0) * MID_ + col]) = pack2(v00, v01);
            *reinterpret_cast<unsigned*>(&dst[((size_t)b * N_ + r0 + 8) * MID_ + col]) = pack2(v10, v11);
        }
    }
}

// ---------------------------------------------------------------------------
// projV: v projection. D[mid][n] = sum_c w[mid][c] x[c][n]
// grid (N/128=16, MID/128=2, B), 256 thr.
// ---------------------------------------------------------------------------
__global__ __launch_bounds__(256, 2) void projV_mma(
    const float* __restrict__ x,
    const float* __restrict__ wv, const float* __restrict__ bv)
{
    __shared__ __align__(16) bf16 As[2][TBM * TSTR];
    __shared__ __align__(16) bf16 Bs[2][TBM * TSTR];

    const int b  = blockIdx.z;
    const int m0 = blockIdx.y * TBM;
    const int n0 = blockIdx.x * TBN;
    const int tid  = threadIdx.x;
    const int lane = tid & 31, wid = tid >> 5;
    const int wm = wid & 1, wn = wid >> 1;
    const int g = lane >> 2, tg = lane & 3;

    const float* xb = x + (size_t)b * C_ * N_;

    float acc[4][4][4] = {};

    stage_f32(As[0], wv + (size_t)m0 * C_, C_, 0, tid);
    stage_xT(Bs[0], xb, 0, n0, tid);
    __syncthreads();

    for (int k0 = 0; k0 < C_; k0 += TBK) {
        const int buf = (k0 / TBK) & 1;
        if (k0 + TBK < C_) {
            stage_f32(As[buf ^ 1], wv + (size_t)m0 * C_, C_, k0 + TBK, tid);
            stage_xT(Bs[buf ^ 1], xb, k0 + TBK, n0, tid);
        }
        mma_tile(As[buf], Bs[buf], acc, wm, wn, lane);
        __syncthreads();
    }

    #pragma unroll
    for (int mt = 0; mt < 4; mt++) {
        int r0 = m0 + wm * 64 + mt * 16 + g;
        int r1 = r0 + 8;
        float b0v = bv[r0], b1v = bv[r1];
        #pragma unroll
        for (int nt = 0; nt < 4; nt++) {
            int col = n0 + wn * 32 + nt * 8 + 2 * tg;
            *reinterpret_cast<unsigned*>(&g_v[((size_t)b * MID_ + r0) * N_ + col]) =
                pack2(acc[mt][nt][0] + b0v, acc[mt][nt][1] + b0v);
            *reinterpret_cast<unsigned*>(&g_v[((size_t)b * MID_ + r1) * N_ + col]) =
                pack2(acc[mt][nt][2] + b1v, acc[mt][nt][3] + b1v);
        }
    }
}

// ---------------------------------------------------------------------------
// scores: S^T[j][i] = (1/16) sum_m k[m][j] q[m][i]
// grid (N/128 i, N/128 j, B), 256 thr.
// ---------------------------------------------------------------------------
__global__ __launch_bounds__(256, 2) void scores_mma()
{
    __shared__ __align__(16) bf16 As[2][TBM * TSTR];
    __shared__ __align__(16) bf16 Bs[2][TBM * TSTR];

    const int b  = blockIdx.z;
    const int j0 = blockIdx.y * TBM;
    const int i0 = blockIdx.x * TBN;
    const int tid  = threadIdx.x;
    const int lane = tid & 31, wid = tid >> 5;
    const int wm = wid & 1, wn = wid >> 1;
    const int g = lane >> 2, tg = lane & 3;

    const bf16* kT = g_kT + ((size_t)b * N_ + j0) * MID_;
    const bf16* qT = g_qT + ((size_t)b * N_ + i0) * MID_;

    float acc[4][4][4] = {};

    stage_bf16(As[0], kT, MID_, 0, tid);
    stage_bf16(Bs[0], qT, MID_, 0, tid);
    __syncthreads();

    for (int k0 = 0; k0 < MID_; k0 += TBK) {
        const int buf = (k0 / TBK) & 1;
        if (k0 + TBK < MID_) {
            stage_bf16(As[buf ^ 1], kT, MID_, k0 + TBK, tid);
            stage_bf16(Bs[buf ^ 1], qT, MID_, k0 + TBK, tid);
        }
        mma_tile(As[buf], Bs[buf], acc, wm, wn, lane);
        __syncthreads();
    }

    #pragma unroll
    for (int mt = 0; mt < 4; mt++) {
        int row = j0 + wm * 64 + mt * 16 + g;
        #pragma unroll
        for (int nt = 0; nt < 4; nt++) {
            int col = i0 + wn * 32 + nt * 8 + 2 * tg;
            *reinterpret_cast<unsigned*>(&g_sT[((size_t)b * N_ + row) * N_ + col]) =
                pack2(acc[mt][nt][0] * 0.0625f, acc[mt][nt][1] * 0.0625f);
            *reinterpret_cast<unsigned*>(&g_sT[((size_t)b * N_ + row + 8) * N_ + col]) =
                pack2(acc[mt][nt][2] * 0.0625f, acc[mt][nt][3] * 0.0625f);
        }
    }
}

// ---------------------------------------------------------------------------
// colreduce: per j, online max/sum-exp over i (S^T row). One warp per row.
// ---------------------------------------------------------------------------
__global__ __launch_bounds__(256) void colreduce_kernel()
{
    const int b = blockIdx.y;
    const int w = threadIdx.x >> 5, lane = threadIdx.x & 31;
    const int j = blockIdx.x * 8 + w;
    const uint4* row = reinterpret_cast<const uint4*>(g_sT + ((size_t)b * N_ + j) * N_);

    float M = -3.0e38f, S = 0.0f;
    #pragma unroll
    for (int it = 0; it < 8; it++) {
        uint4 rv = row[lane + 32 * it];
        const unsigned u[4] = {rv.x, rv.y, rv.z, rv.w};
        #pragma unroll
        for (int q = 0; q < 4; q++) {
            float2 f = __bfloat1622float2(*reinterpret_cast<const bf162*>(&u[q]));
            float mn = fmaxf(M, f.x);
            S = S * __expf(M - mn) + __expf(f.x - mn); M = mn;
            mn = fmaxf(M, f.y);
            S = S * __expf(M - mn) + __expf(f.y - mn); M = mn;
        }
    }
    #pragma unroll
    for (int off = 16; off > 0; off >>= 1) {
        float om = __shfl_xor_sync(0xffffffffu, M, off);
        float os = __shfl_xor_sync(0xffffffffu, S, off);
        float mn = fmaxf(M, om);
        S = S * __expf(M - mn) + os * __expf(om - mn);
        M = mn;
    }
    if (lane == 0) {
        g_cmax[b * N_ + j] = M;
        g_cinv[b * N_ + j] = 1.0f / S;
    }
}

// ---------------------------------------------------------------------------
// ctx: ctx^T[j][c] = sum_i P[i][j] v[c][i],  P = exp(S^T[j][i]-cm[j])*ci[j]
// grid (MID/128=2, N/128=16, B), 256 thr.
// ---------------------------------------------------------------------------
__global__ __launch_bounds__(256, 2) void ctx_mma()
{
    __shared__ __align__(16) bf16 As[2][TBM * TSTR];
    __shared__ __align__(16) bf16 Bs[2][TBM * TSTR];
    __shared__ float cmS[TBM], ciS[TBM];

    const int b  = blockIdx.z;
    const int j0 = blockIdx.y * TBM;
    const int c0 = blockIdx.x * TBN;
    const int tid  = threadIdx.x;
    const int lane = tid & 31, wid = tid >> 5;
    const int wm = wid & 1, wn = wid >> 1;
    const int g = lane >> 2, tg = lane & 3;

    if (tid < TBM) {
        cmS[tid] = g_cmax[b * N_ + j0 + tid];
        ciS[tid] = g_cinv[b * N_ + j0 + tid];
    }
    __syncthreads();

    const bf16* sT = g_sT + ((size_t)b * N_ + j0) * N_;
    const bf16* vb = g_v + ((size_t)b * MID_ + c0) * N_;

    float acc[4][4][4] = {};

    auto stage_P = [&](bf16* T, int k0) {
        #pragma unroll
        for (int r = 0; r < 2; r++) {
            int f = tid + r * 256;
            int j = f >> 2, i8 = (f & 3) * 8;
            uint4 raw = *reinterpret_cast<const uint4*>(&sT[(size_t)j * N_ + k0 + i8]);
            const unsigned u[4] = {raw.x, raw.y, raw.z, raw.w};
            float cm = cmS[j], ci = ciS[j];
            uint4 outp;
            unsigned po[4];
            #pragma unroll
            for (int q = 0; q < 4; q++) {
                float2 fv = __bfloat1622float2(*reinterpret_cast<const bf162*>(&u[q]));
                po[q] = pack2(__expf(fv.x - cm) * ci, __expf(fv.y - cm) * ci);
            }
            outp.x = po[0]; outp.y = po[1]; outp.z = po[2]; outp.w = po[3];
            *reinterpret_cast<uint4*>(&T[j * TSTR + i8]) = outp;
        }
    };

    stage_P(As[0], 0);
    stage_bf16(Bs[0], vb, N_, 0, tid);
    __syncthreads();

    for (int k0 = 0; k0 < N_; k0 += TBK) {
        const int buf = (k0 / TBK) & 1;
        if (k0 + TBK < N_) {
            stage_P(As[buf ^ 1], k0 + TBK);
            stage_bf16(Bs[buf ^ 1], vb, N_, k0 + TBK, tid);
        }
        mma_tile(As[buf], Bs[buf], acc, wm, wn, lane);
        __syncthreads();
    }

    #pragma unroll
    for (int mt = 0; mt < 4; mt++) {
        int row = j0 + wm * 64 + mt * 16 + g;
        #pragma unroll
        for (int nt = 0; nt < 4; nt++) {
            int col = c0 + wn * 32 + nt * 8 + 2 * tg;
            *reinterpret_cast<unsigned*>(&g_ctxT[((size_t)b * N_ + row) * MID_ + col]) =
                pack2(acc[mt][nt][0], acc[mt][nt][1]);
            *reinterpret_cast<unsigned*>(&g_ctxT[((size_t)b * N_ + row + 8) * MID_ + col]) =
                pack2(acc[mt][nt][2], acc[mt][nt][3]);
        }
    }
}

// ---------------------------------------------------------------------------
// out: out[c'][n] = x + sum_m wo[c'][m] ctx^T[n][m] + bo[c']
// grid (N/128=16, C/128=4, B), 256 thr.
// ---------------------------------------------------------------------------
__global__ __launch_bounds__(256, 2) void out_mma(
    const float* __restrict__ x,
    const float* __restrict__ wo,
    const float* __restrict__ bo,
    float* __restrict__ out)
{
    __shared__ __align__(16) bf16 As[2][TBM * TSTR];
    __shared__ __align__(16) bf16 Bs[2][TBM * TSTR];

    const int b  = blockIdx.z;
    const int m0 = blockIdx.y * TBM;
    const int n0 = blockIdx.x * TBN;
    const int tid  = threadIdx.x;
    const int lane = tid & 31, wid = tid >> 5;
    const int wm = wid & 1, wn = wid >> 1;
    const int g = lane >> 2, tg = lane & 3;

    const bf16* cT = g_ctxT + ((size_t)b * N_ + n0) * MID_;

    float acc[4][4][4] = {};

    stage_f32(As[0], wo + (size_t)m0 * MID_, MID_, 0, tid);
    stage_bf16(Bs[0], cT, MID_, 0, tid);
    __syncthreads();

    for (int k0 = 0; k0 < MID_; k0 += TBK) {
        const int buf = (k0 / TBK) & 1;
        if (k0 + TBK < MID_) {
            stage_f32(As[buf ^ 1], wo + (size_t)m0 * MID_, MID_, k0 + TBK, tid);
            stage_bf16(Bs[buf ^ 1], cT, MID_, k0 + TBK, tid);
        }
        mma_tile(As[buf], Bs[buf], acc, wm, wn, lane);
        __syncthreads();
    }

    #pragma unroll
    for (int mt = 0; mt < 4; mt++) {
        int r0 = m0 + wm * 64 + mt * 16 + g;
        int r1 = r0 + 8;
        float bo0 = bo[r0], bo1 = bo[r1];
        #pragma unroll
        for (int nt = 0; nt < 4; nt++) {
            int col = n0 + wn * 32 + nt * 8 + 2 * tg;
            size_t a0 = ((size_t)b * C_ + r0) * N_ + col;
            size_t a1 = ((size_t)b * C_ + r1) * N_ + col;
            float2 x0 = *reinterpret_cast<const float2*>(&x[a0]);
            float2 x1 = *reinterpret_cast<const float2*>(&x[a1]);
            float2 v0 = {acc[mt][nt][0] + bo0 + x0.x, acc[mt][nt][1] + bo0 + x0.y};
            float2 v1 = {acc[mt][nt][2] + bo1 + x1.x, acc[mt][nt][3] + bo1 + x1.y};
            *reinterpret_cast<float2*>(&out[a0]) = v0;
            *reinterpret_cast<float2*>(&out[a1]) = v1;
        }
    }
}

// ---------------------------------------------------------------------------
extern "C" void kernel_launch(void* const* d_in, const int* in_sizes, int n_in,
                              void* d_out, int out_size)
{
    (void)in_sizes; (void)n_in; (void)out_size;
    const float* x     = (const float*)d_in[0];
    const float* wq    = (const float*)d_in[1];
    const float* bq    = (const float*)d_in[2];
    const float* gq    = (const float*)d_in[3];
    const float* betaq = (const float*)d_in[4];
    const float* wk    = (const float*)d_in[5];
    const float* bk    = (const float*)d_in[6];
    const float* gk    = (const float*)d_in[7];
    const float* betak = (const float*)d_in[8];
    const float* wv    = (const float*)d_in[9];
    const float* bv    = (const float*)d_in[10];
    const float* wo    = (const float*)d_in[11];
    const float* bo    = (const float*)d_in[12];
    const float* mq    = (const float*)d_in[13];
    const float* vq    = (const float*)d_in[14];
    const float* mk    = (const float*)d_in[15];
    const float* vk    = (const float*)d_in[16];
    float* out = (float*)d_out;

    dim3 blk(256);
    projT_mma<<<dim3(MID_/TBN, N_/TBM, 2*B_), blk>>>(
        x, wq, bq, gq, betaq, mq, vq, wk, bk, gk, betak, mk, vk);
    projV_mma<<<dim3(N_/TBN, MID_/TBM, B_), blk>>>(x, wv, bv);
    scores_mma<<<dim3(N_/TBN, N_/TBM, B_), blk>>>();
    colreduce_kernel<<<dim3(N_/8, B_), blk>>>();
    ctx_mma<<<dim3(MID_/TBN, N_/TBM, B_), blk>>>();
    out_mma<<<dim3(N_/TBN, C_/TBM, B_), blk>>>(x, wo, bo, out);
}